// round 2
// baseline (speedup 1.0000x reference)
#include <cuda_runtime.h>

// MultiHeadAttention: B=4, S=2048, D_IN=1024, H=16, D_HEAD=64
// Pipeline (all fp32 for first passing baseline):
//   1. wtrans:   repack Wq/Wk/Wv [H,DIN,DH] -> [DIN, H*DH] contiguous
//   2. sgemm x3: Q/K/V = X @ Wt + b   ([8192,1024] x [1024,1024])
//                written in "concat layout" [B*S, H*DH] so heads are
//                column slices (attention reads with head offset h*64)
//   3. flash_attn: per (b,h,qblock=64) online-softmax attention
//   4. sgemm:    out = O_concat @ Wo + bo  -> d_out

#define BB   4
#define SS   2048
#define DIN  1024
#define HH   16
#define DH   64
#define MROWS (BB * SS)          // 8192

// ---------------- scratch (device globals; no cudaMalloc allowed) -----------
__device__ float g_Q[MROWS * DIN];
__device__ float g_K[MROWS * DIN];
__device__ float g_V[MROWS * DIN];
__device__ float g_O[MROWS * DIN];
__device__ float g_Wt[3][DIN * DIN];

// ---------------- weight repack: Wt[i, h*64+d] = W[h, i, d] -----------------
__global__ void wtrans_kernel(const float* __restrict__ Wq,
                              const float* __restrict__ Wk,
                              const float* __restrict__ Wv) {
    int idx = blockIdx.x * blockDim.x + threadIdx.x;   // over DIN*DIN
    const float* src = (blockIdx.y == 0) ? Wq : (blockIdx.y == 1) ? Wk : Wv;
    int i = idx >> 10;          // input dim
    int n = idx & 1023;         // h*64 + d
    int h = n >> 6;
    int d = n & 63;
    g_Wt[blockIdx.y][idx] = src[(h * DIN + i) * DH + d];
}

// ---------------- tiled SGEMM: C[M,N] = A[M,K] @ B[K,N] + bias[N] -----------
// BM=128, BN=128, BK=8, 256 threads, 8x8 register tile per thread.
__global__ __launch_bounds__(256) void sgemm_bias(
    const float* __restrict__ A, const float* __restrict__ Bm,
    const float* __restrict__ bias, float* __restrict__ C,
    int M, int N, int K)
{
    __shared__ float As[8][132];   // [k][m], padded (132*4B % 16 == 0)
    __shared__ float Bs[8][128];   // [k][n]

    const int t  = threadIdx.x;
    const int tx = t & 15;         // 0..15 -> col tile
    const int ty = t >> 4;         // 0..15 -> row tile
    const int m0 = blockIdx.y * 128;
    const int n0 = blockIdx.x * 128;

    // loader indices
    const int arow = t >> 1;           // 0..127
    const int ak   = (t & 1) * 4;      // 0 or 4
    const int brow = t >> 5;           // 0..7
    const int bn   = (t & 31) * 4;     // 0..124

    float acc[8][8];
#pragma unroll
    for (int i = 0; i < 8; i++)
#pragma unroll
        for (int j = 0; j < 8; j++) acc[i][j] = 0.f;

    for (int k0 = 0; k0 < K; k0 += 8) {
        float4 av = *(const float4*)(A + (long)(m0 + arow) * K + k0 + ak);
        As[ak + 0][arow] = av.x;
        As[ak + 1][arow] = av.y;
        As[ak + 2][arow] = av.z;
        As[ak + 3][arow] = av.w;
        *(float4*)(&Bs[brow][bn]) =
            *(const float4*)(Bm + (long)(k0 + brow) * N + n0 + bn);
        __syncthreads();

#pragma unroll
        for (int k = 0; k < 8; k++) {
            float4 ra0 = *(const float4*)(&As[k][ty * 8]);
            float4 ra1 = *(const float4*)(&As[k][ty * 8 + 4]);
            float4 rb0 = *(const float4*)(&Bs[k][tx * 8]);
            float4 rb1 = *(const float4*)(&Bs[k][tx * 8 + 4]);
            float ra[8] = {ra0.x, ra0.y, ra0.z, ra0.w, ra1.x, ra1.y, ra1.z, ra1.w};
            float rb[8] = {rb0.x, rb0.y, rb0.z, rb0.w, rb1.x, rb1.y, rb1.z, rb1.w};
#pragma unroll
            for (int i = 0; i < 8; i++)
#pragma unroll
                for (int j = 0; j < 8; j++)
                    acc[i][j] = fmaf(ra[i], rb[j], acc[i][j]);
        }
        __syncthreads();
    }

#pragma unroll
    for (int i = 0; i < 8; i++) {
        long row = m0 + ty * 8 + i;
#pragma unroll
        for (int j = 0; j < 8; j += 4) {
            int col = n0 + tx * 8 + j;
            float4 v;
            v.x = acc[i][j + 0] + bias[col + 0];
            v.y = acc[i][j + 1] + bias[col + 1];
            v.z = acc[i][j + 2] + bias[col + 2];
            v.w = acc[i][j + 3] + bias[col + 3];
            *(float4*)(C + row * N + col) = v;
        }
    }
}

// ---------------- flash attention -------------------------------------------
// Grid: (S/64, H, B). 256 threads as 16x16; each thread owns a 4x4 tile of
// the 64(q) x 64(k) score block and a 4x4 tile of the 64(q) x 64(d) output.
// Smem: Qs[d][q] (65), Ks[d][k] (65), Ps[q][k] (65), Vs[k][d] (68).
#define ST  65
#define STV 68
#define SMEM_FA ((3 * 64 * ST + 64 * STV) * 4)

__global__ __launch_bounds__(256) void flash_attn_kernel() {
    extern __shared__ float sm[];
    float* Qs = sm;
    float* Ks = sm + 64 * ST;
    float* Ps = sm + 2 * 64 * ST;
    float* Vs = sm + 3 * 64 * ST;

    const int t  = threadIdx.x;
    const int tx = t & 15;
    const int ty = t >> 4;
    const int b  = blockIdx.z;
    const int h  = blockIdx.y;
    const int q0 = blockIdx.x * 64;

    const long base_q = (long)(b * SS + q0) * DIN + h * DH;

    // load Q tile transposed: Qs[d][row]
#pragma unroll
    for (int rep = 0; rep < 4; rep++) {
        int idx = rep * 256 + t;
        int row = idx >> 4;
        int c4  = idx & 15;
        float4 v = *(const float4*)(g_Q + base_q + (long)row * DIN + c4 * 4);
        Qs[(c4 * 4 + 0) * ST + row] = v.x;
        Qs[(c4 * 4 + 1) * ST + row] = v.y;
        Qs[(c4 * 4 + 2) * ST + row] = v.z;
        Qs[(c4 * 4 + 3) * ST + row] = v.w;
    }

    float m_i[4], l_i[4], o[4][4];
#pragma unroll
    for (int i = 0; i < 4; i++) {
        m_i[i] = -1e30f;
        l_i[i] = 0.f;
#pragma unroll
        for (int j = 0; j < 4; j++) o[i][j] = 0.f;
    }

    for (int kb = 0; kb < SS / 64; kb++) {
        const long base_k = (long)(b * SS + kb * 64) * DIN + h * DH;
#pragma unroll
        for (int rep = 0; rep < 4; rep++) {
            int idx = rep * 256 + t;
            int row = idx >> 4;
            int c4  = idx & 15;
            float4 kv = *(const float4*)(g_K + base_k + (long)row * DIN + c4 * 4);
            Ks[(c4 * 4 + 0) * ST + row] = kv.x;
            Ks[(c4 * 4 + 1) * ST + row] = kv.y;
            Ks[(c4 * 4 + 2) * ST + row] = kv.z;
            Ks[(c4 * 4 + 3) * ST + row] = kv.w;
            float4 vv = *(const float4*)(g_V + base_k + (long)row * DIN + c4 * 4);
            *(float4*)(Vs + row * STV + c4 * 4) = vv;
        }
        __syncthreads();

        // GEMM1: s = (Q tile) . (K tile)^T
        float s[4][4];
#pragma unroll
        for (int i = 0; i < 4; i++)
#pragma unroll
            for (int j = 0; j < 4; j++) s[i][j] = 0.f;

        for (int d = 0; d < 64; d++) {
            float qa[4], ka[4];
#pragma unroll
            for (int i = 0; i < 4; i++) qa[i] = Qs[d * ST + ty * 4 + i];
#pragma unroll
            for (int j = 0; j < 4; j++) ka[j] = Ks[d * ST + tx * 4 + j];
#pragma unroll
            for (int i = 0; i < 4; i++)
#pragma unroll
                for (int j = 0; j < 4; j++)
                    s[i][j] = fmaf(qa[i], ka[j], s[i][j]);
        }

        // online softmax (scale 1/sqrt(64) = 0.125)
#pragma unroll
        for (int i = 0; i < 4; i++) {
#pragma unroll
            for (int j = 0; j < 4; j++) s[i][j] *= 0.125f;

            float rm = fmaxf(fmaxf(s[i][0], s[i][1]), fmaxf(s[i][2], s[i][3]));
            rm = fmaxf(rm, __shfl_xor_sync(0xffffffffu, rm, 1));
            rm = fmaxf(rm, __shfl_xor_sync(0xffffffffu, rm, 2));
            rm = fmaxf(rm, __shfl_xor_sync(0xffffffffu, rm, 4));
            rm = fmaxf(rm, __shfl_xor_sync(0xffffffffu, rm, 8));

            float mnew  = fmaxf(m_i[i], rm);
            float alpha = __expf(m_i[i] - mnew);
            float rs = 0.f;
#pragma unroll
            for (int j = 0; j < 4; j++) {
                s[i][j] = __expf(s[i][j] - mnew);
                rs += s[i][j];
            }
            rs += __shfl_xor_sync(0xffffffffu, rs, 1);
            rs += __shfl_xor_sync(0xffffffffu, rs, 2);
            rs += __shfl_xor_sync(0xffffffffu, rs, 4);
            rs += __shfl_xor_sync(0xffffffffu, rs, 8);

            l_i[i] = l_i[i] * alpha + rs;
            m_i[i] = mnew;
#pragma unroll
            for (int j = 0; j < 4; j++) o[i][j] *= alpha;
#pragma unroll
            for (int j = 0; j < 4; j++)
                Ps[(ty * 4 + i) * ST + tx * 4 + j] = s[i][j];
        }
        __syncthreads();

        // GEMM2: O += P . V
        for (int kk = 0; kk < 64; kk++) {
            float pa[4];
#pragma unroll
            for (int i = 0; i < 4; i++) pa[i] = Ps[(ty * 4 + i) * ST + kk];
            float4 vb = *(const float4*)(Vs + kk * STV + tx * 4);
            float vbv[4] = {vb.x, vb.y, vb.z, vb.w};
#pragma unroll
            for (int i = 0; i < 4; i++)
#pragma unroll
                for (int j = 0; j < 4; j++)
                    o[i][j] = fmaf(pa[i], vbv[j], o[i][j]);
        }
        __syncthreads();
    }

    // epilogue: normalize and write to concat layout [B*S, H*DH]
#pragma unroll
    for (int i = 0; i < 4; i++) {
        float inv = 1.0f / l_i[i];
        long row = (long)(b * SS + q0 + ty * 4 + i);
        float4 v;
        v.x = o[i][0] * inv;
        v.y = o[i][1] * inv;
        v.z = o[i][2] * inv;
        v.w = o[i][3] * inv;
        *(float4*)(g_O + row * DIN + h * DH + tx * 4) = v;
    }
}

// ---------------- launcher ---------------------------------------------------
extern "C" void kernel_launch(void* const* d_in, const int* in_sizes, int n_in,
                              void* d_out, int out_size) {
    const float* query = (const float*)d_in[0];
    const float* key_  = (const float*)d_in[1];
    const float* value = (const float*)d_in[2];
    // d_in[3]=Wq, [4]=bq, [5]=Wk, [6]=bk, [7]=Wv, [8]=bv, [9]=Wo, [10]=bo
    const float* Wq = (const float*)d_in[3];
    const float* bq = (const float*)d_in[4];
    const float* Wk = (const float*)d_in[5];
    const float* bk = (const float*)d_in[6];
    const float* Wv = (const float*)d_in[7];
    const float* bv = (const float*)d_in[8];
    const float* Wo = (const float*)d_in[9];
    const float* bo = (const float*)d_in[10];
    float* out = (float*)d_out;

    float *pQ, *pK, *pV, *pO, *pW;
    cudaGetSymbolAddress((void**)&pQ, g_Q);
    cudaGetSymbolAddress((void**)&pK, g_K);
    cudaGetSymbolAddress((void**)&pV, g_V);
    cudaGetSymbolAddress((void**)&pO, g_O);
    cudaGetSymbolAddress((void**)&pW, g_Wt);

    cudaFuncSetAttribute(flash_attn_kernel,
                         cudaFuncAttributeMaxDynamicSharedMemorySize, SMEM_FA);

    wtrans_kernel<<<dim3(DIN * DIN / 256, 3), 256>>>(Wq, Wk, Wv);

    dim3 gg(DIN / 128, MROWS / 128);
    sgemm_bias<<<gg, 256>>>(query, pW + 0 * DIN * DIN, bq, pQ, MROWS, DIN, DIN);
    sgemm_bias<<<gg, 256>>>(key_,  pW + 1 * DIN * DIN, bk, pK, MROWS, DIN, DIN);
    sgemm_bias<<<gg, 256>>>(value, pW + 2 * DIN * DIN, bv, pV, MROWS, DIN, DIN);

    flash_attn_kernel<<<dim3(SS / 64, HH, BB), 256, SMEM_FA>>>();

    sgemm_bias<<<gg, 256>>>(pO, Wo, bo, out, MROWS, DIN, DIN);
}

// round 4
// speedup vs baseline: 1.3504x; 1.3504x over previous
#include <cuda_runtime.h>
#include <cuda_bf16.h>
#include <cstdint>

// MultiHeadAttention: B=4, S=2048, D_IN=1024, H=16, D_HEAD=64
// Round 4: harness targets compute_100 (no tcgen05!). Four big GEMMs use
// mma.sync.m16n8k16 bf16 (arch-generic tensor path) with 2-term bf16 split:
//   A@B = Ah@Bh + Ah@Bl + Al@Bh  (fp32 accum; err ~1e-5 << 1e-3 budget)
// Flash attention remains fp32 (unchanged from passing round 2).

#define BB   4
#define SS   2048
#define DIN  1024
#define HH   16
#define DH   64
#define MROWS (BB * SS)          // 8192

// ---------------- scratch (device globals; no cudaMalloc allowed) -----------
__device__ float g_Q[MROWS * DIN];
__device__ float g_K[MROWS * DIN];
__device__ float g_V[MROWS * DIN];
__device__ float g_O[MROWS * DIN];
__device__ __nv_bfloat16 g_Xh[MROWS * DIN];     // activation split hi
__device__ __nv_bfloat16 g_Xl[MROWS * DIN];     // activation split lo
__device__ __nv_bfloat16 g_Wh[4][DIN * DIN];    // weights^T split hi ([N,K] k-contig)
__device__ __nv_bfloat16 g_Wl[4][DIN * DIN];    // weights^T split lo

// ============================ mma helpers ====================================
__device__ __forceinline__ uint32_t smem_u32(const void* p) {
    return (uint32_t)__cvta_generic_to_shared((void*)p);
}
__device__ __forceinline__ void ldsm4(uint32_t* r, uint32_t addr) {
    asm volatile("ldmatrix.sync.aligned.m8n8.x4.shared.b16 {%0,%1,%2,%3}, [%4];"
                 : "=r"(r[0]), "=r"(r[1]), "=r"(r[2]), "=r"(r[3]) : "r"(addr));
}
__device__ __forceinline__ void mma16816(float* d, const uint32_t* a, const uint32_t* b) {
    asm volatile(
        "mma.sync.aligned.m16n8k16.row.col.f32.bf16.bf16.f32 "
        "{%0,%1,%2,%3}, {%4,%5,%6,%7}, {%8,%9}, {%0,%1,%2,%3};"
        : "+f"(d[0]), "+f"(d[1]), "+f"(d[2]), "+f"(d[3])
        : "r"(a[0]), "r"(a[1]), "r"(a[2]), "r"(a[3]), "r"(b[0]), "r"(b[1]));
}

// ====================== fp32 -> bf16 split converters ========================
__global__ void split_x_kernel(const float4* __restrict__ X,
                               __nv_bfloat16* __restrict__ Xh,
                               __nv_bfloat16* __restrict__ Xl) {
    long i = (long)blockIdx.x * 256 + threadIdx.x;       // over MROWS*DIN/4
    float4 v = X[i];
    float xs[4] = {v.x, v.y, v.z, v.w};
    __nv_bfloat16 h[4], l[4];
#pragma unroll
    for (int j = 0; j < 4; j++) {
        h[j] = __float2bfloat16(xs[j]);
        l[j] = __float2bfloat16(xs[j] - __bfloat162float(h[j]));
    }
    *(uint2*)(Xh + i * 4) = *(uint2*)h;
    *(uint2*)(Xl + i * 4) = *(uint2*)l;
}

// weights: produce B operand layout [N=1024 rows, K=1024 cols] k-contiguous.
// m=0..2: B[n][k] = Wsrc[h, k, d] with n = h*64+d; m=3: B[n][k] = Wo[k, n]
__global__ void wsplit_kernel(const float* __restrict__ Wq,
                              const float* __restrict__ Wk,
                              const float* __restrict__ Wv,
                              const float* __restrict__ Wo) {
    int m = blockIdx.y;
    int idx = blockIdx.x * 256 + threadIdx.x;   // n*1024 + k
    int k = idx & 1023;
    int n = idx >> 10;
    float x;
    if (m < 3) {
        const float* W = (m == 0) ? Wq : (m == 1) ? Wk : Wv;
        int h = n >> 6, d = n & 63;
        x = W[((long)h * DIN + k) * DH + d];
    } else {
        x = Wo[(long)k * DIN + n];
    }
    __nv_bfloat16 hi = __float2bfloat16(x);
    g_Wh[m][idx] = hi;
    g_Wl[m][idx] = __float2bfloat16(x - __bfloat162float(hi));
}

// ============== mma.sync GEMM: C = (Ah+Al)(Bh+Bl)^T + bias ===================
// BM=128, BN=128, KC=32. 256 threads = 8 warps (2x4), warp tile 64x32.
// smem per stage: 4 tiles (Ah,Al,Bh,Bl) of 128 x 32 bf16, row stride 40
// (80B, 16B-aligned, conflict-free for ldmatrix). Double buffered: 80KB.
#define KC    32
#define ASTR  40
#define TILE_UNITS (128 * ASTR)            // 5120 bf16 per tile
#define STAGE_UNITS (4 * TILE_UNITS)       // 20480
#define SMEM_GEMM (2 * STAGE_UNITS * 2)    // 81920 bytes

__device__ __forceinline__ void load_tile4(__nv_bfloat16* smem, int stage,
                                           const __nv_bfloat16* const* srcs,
                                           int k0, int t) {
#pragma unroll
    for (int w = 0; w < 4; w++) {
        __nv_bfloat16* dst = smem + stage * STAGE_UNITS + w * TILE_UNITS;
        const __nv_bfloat16* src = srcs[w] + k0;
#pragma unroll
        for (int i = 0; i < 4; i++) {
            int u = t + 256 * i;          // 0..1023 (128 rows x 8 uint2)
            int r = u >> 3;
            int c = u & 7;
            *(uint2*)(dst + r * ASTR + c * 4) =
                *(const uint2*)(src + (long)r * DIN + c * 4);
        }
    }
}

__global__ __launch_bounds__(256) void gemm_mma(
    const __nv_bfloat16* __restrict__ Ah, const __nv_bfloat16* __restrict__ Al,
    const __nv_bfloat16* __restrict__ Bh, const __nv_bfloat16* __restrict__ Bl,
    const float* __restrict__ bias, float* __restrict__ C)
{
    extern __shared__ __nv_bfloat16 smem[];
    const uint32_t sb = smem_u32(smem);
    const int t = threadIdx.x, wid = t >> 5, lane = t & 31;
    const int m0 = blockIdx.y * 128, n0 = blockIdx.x * 128;
    const int wm = (wid >> 2) * 64;       // warp m offset (0 or 64)
    const int wn = (wid & 3) * 32;        // warp n offset

    // ldmatrix lane->address components
    const int a_r  = (lane & 7) + ((lane >> 3) & 1) * 8;   // row within 16
    const int a_kk = (lane >> 4) * 8;                       // k sub-block
    const int b_n  = (lane & 7) + (lane >> 4) * 8;          // n within 16
    const int b_kk = ((lane >> 3) & 1) * 8;

    const __nv_bfloat16* srcs[4] = {
        Ah + (long)m0 * DIN, Al + (long)m0 * DIN,
        Bh + (long)n0 * DIN, Bl + (long)n0 * DIN };

    float acc[4][4][4];
#pragma unroll
    for (int i = 0; i < 4; i++)
#pragma unroll
        for (int j = 0; j < 4; j++)
#pragma unroll
            for (int e = 0; e < 4; e++) acc[i][j][e] = 0.f;

    load_tile4(smem, 0, srcs, 0, t);
    __syncthreads();

    const int NC = DIN / KC;   // 32
    for (int c = 0; c < NC; c++) {
        const int cur = c & 1;
        if (c + 1 < NC) load_tile4(smem, 1 - cur, srcs, (c + 1) * KC, t);

        const uint32_t stage_b = sb + cur * (STAGE_UNITS * 2);
#pragma unroll
        for (int ks = 0; ks < 2; ks++) {
            uint32_t ah[4][4], al[4][4], bh[2][4], bl[2][4];
#pragma unroll
            for (int mf = 0; mf < 4; mf++) {
                uint32_t off = (uint32_t)((wm + mf * 16 + a_r) * ASTR + ks * 16 + a_kk) * 2;
                ldsm4(ah[mf], stage_b + off);
                ldsm4(al[mf], stage_b + TILE_UNITS * 2 + off);
            }
#pragma unroll
            for (int nf2 = 0; nf2 < 2; nf2++) {
                uint32_t off = (uint32_t)((wn + nf2 * 16 + b_n) * ASTR + ks * 16 + b_kk) * 2;
                ldsm4(bh[nf2], stage_b + TILE_UNITS * 4 + off);
                ldsm4(bl[nf2], stage_b + TILE_UNITS * 6 + off);
            }
#pragma unroll
            for (int mf = 0; mf < 4; mf++)
#pragma unroll
                for (int nf = 0; nf < 4; nf++) {
                    const uint32_t* bhf = &bh[nf >> 1][(nf & 1) * 2];
                    const uint32_t* blf = &bl[nf >> 1][(nf & 1) * 2];
                    mma16816(acc[mf][nf], ah[mf], bhf);
                    mma16816(acc[mf][nf], ah[mf], blf);
                    mma16816(acc[mf][nf], al[mf], bhf);
                }
        }
        __syncthreads();
    }

    // epilogue: c0,c1 -> (m=lane/4, n=(lane%4)*2+{0,1}); c2,c3 -> m+8
    const int em = lane >> 2;
    const int en = (lane & 3) * 2;
#pragma unroll
    for (int mf = 0; mf < 4; mf++) {
#pragma unroll
        for (int half = 0; half < 2; half++) {
            long row = m0 + wm + mf * 16 + em + half * 8;
            float* crow = C + row * DIN;
#pragma unroll
            for (int nf = 0; nf < 4; nf++) {
                int col = n0 + wn + nf * 8 + en;
                float2 v;
                v.x = acc[mf][nf][half * 2 + 0] + bias[col + 0];
                v.y = acc[mf][nf][half * 2 + 1] + bias[col + 1];
                *(float2*)(crow + col) = v;
            }
        }
    }
}

// ======================= flash attention (fp32, unchanged) ===================
#define ST  65
#define STV 68
#define SMEM_FA ((3 * 64 * ST + 64 * STV) * 4)

__global__ __launch_bounds__(256) void flash_attn_kernel() {
    extern __shared__ float sm[];
    float* Qs = sm;
    float* Ks = sm + 64 * ST;
    float* Ps = sm + 2 * 64 * ST;
    float* Vs = sm + 3 * 64 * ST;

    const int t  = threadIdx.x;
    const int tx = t & 15;
    const int ty = t >> 4;
    const int b  = blockIdx.z;
    const int h  = blockIdx.y;
    const int q0 = blockIdx.x * 64;

    const long base_q = (long)(b * SS + q0) * DIN + h * DH;

#pragma unroll
    for (int rep = 0; rep < 4; rep++) {
        int idx = rep * 256 + t;
        int row = idx >> 4;
        int c4  = idx & 15;
        float4 v = *(const float4*)(g_Q + base_q + (long)row * DIN + c4 * 4);
        Qs[(c4 * 4 + 0) * ST + row] = v.x;
        Qs[(c4 * 4 + 1) * ST + row] = v.y;
        Qs[(c4 * 4 + 2) * ST + row] = v.z;
        Qs[(c4 * 4 + 3) * ST + row] = v.w;
    }

    float m_i[4], l_i[4], o[4][4];
#pragma unroll
    for (int i = 0; i < 4; i++) {
        m_i[i] = -1e30f;
        l_i[i] = 0.f;
#pragma unroll
        for (int j = 0; j < 4; j++) o[i][j] = 0.f;
    }

    for (int kb = 0; kb < SS / 64; kb++) {
        const long base_k = (long)(b * SS + kb * 64) * DIN + h * DH;
#pragma unroll
        for (int rep = 0; rep < 4; rep++) {
            int idx = rep * 256 + t;
            int row = idx >> 4;
            int c4  = idx & 15;
            float4 kv = *(const float4*)(g_K + base_k + (long)row * DIN + c4 * 4);
            Ks[(c4 * 4 + 0) * ST + row] = kv.x;
            Ks[(c4 * 4 + 1) * ST + row] = kv.y;
            Ks[(c4 * 4 + 2) * ST + row] = kv.z;
            Ks[(c4 * 4 + 3) * ST + row] = kv.w;
            float4 vv = *(const float4*)(g_V + base_k + (long)row * DIN + c4 * 4);
            *(float4*)(Vs + row * STV + c4 * 4) = vv;
        }
        __syncthreads();

        float s[4][4];
#pragma unroll
        for (int i = 0; i < 4; i++)
#pragma unroll
            for (int j = 0; j < 4; j++) s[i][j] = 0.f;

        for (int d = 0; d < 64; d++) {
            float qa[4], ka[4];
#pragma unroll
            for (int i = 0; i < 4; i++) qa[i] = Qs[d * ST + ty * 4 + i];
#pragma unroll
            for (int j = 0; j < 4; j++) ka[j] = Ks[d * ST + tx * 4 + j];
#pragma unroll
            for (int i = 0; i < 4; i++)
#pragma unroll
                for (int j = 0; j < 4; j++)
                    s[i][j] = fmaf(qa[i], ka[j], s[i][j]);
        }

#pragma unroll
        for (int i = 0; i < 4; i++) {
#pragma unroll
            for (int j = 0; j < 4; j++) s[i][j] *= 0.125f;

            float rm = fmaxf(fmaxf(s[i][0], s[i][1]), fmaxf(s[i][2], s[i][3]));
            rm = fmaxf(rm, __shfl_xor_sync(0xffffffffu, rm, 1));
            rm = fmaxf(rm, __shfl_xor_sync(0xffffffffu, rm, 2));
            rm = fmaxf(rm, __shfl_xor_sync(0xffffffffu, rm, 4));
            rm = fmaxf(rm, __shfl_xor_sync(0xffffffffu, rm, 8));

            float mnew  = fmaxf(m_i[i], rm);
            float alpha = __expf(m_i[i] - mnew);
            float rs = 0.f;
#pragma unroll
            for (int j = 0; j < 4; j++) {
                s[i][j] = __expf(s[i][j] - mnew);
                rs += s[i][j];
            }
            rs += __shfl_xor_sync(0xffffffffu, rs, 1);
            rs += __shfl_xor_sync(0xffffffffu, rs, 2);
            rs += __shfl_xor_sync(0xffffffffu, rs, 4);
            rs += __shfl_xor_sync(0xffffffffu, rs, 8);

            l_i[i] = l_i[i] * alpha + rs;
            m_i[i] = mnew;
#pragma unroll
            for (int j = 0; j < 4; j++) o[i][j] *= alpha;
#pragma unroll
            for (int j = 0; j < 4; j++)
                Ps[(ty * 4 + i) * ST + tx * 4 + j] = s[i][j];
        }
        __syncthreads();

        for (int kk = 0; kk < 64; kk++) {
            float pa[4];
#pragma unroll
            for (int i = 0; i < 4; i++) pa[i] = Ps[(ty * 4 + i) * ST + kk];
            float4 vb = *(const float4*)(Vs + kk * STV + tx * 4);
            float vbv[4] = {vb.x, vb.y, vb.z, vb.w};
#pragma unroll
            for (int i = 0; i < 4; i++)
#pragma unroll
                for (int j = 0; j < 4; j++)
                    o[i][j] = fmaf(pa[i], vbv[j], o[i][j]);
        }
        __syncthreads();
    }

#pragma unroll
    for (int i = 0; i < 4; i++) {
        float inv = 1.0f / l_i[i];
        long row = (long)(b * SS + q0 + ty * 4 + i);
        float4 v;
        v.x = o[i][0] * inv;
        v.y = o[i][1] * inv;
        v.z = o[i][2] * inv;
        v.w = o[i][3] * inv;
        *(float4*)(g_O + row * DIN + h * DH + tx * 4) = v;
    }
}

// ---------------- launcher ---------------------------------------------------
extern "C" void kernel_launch(void* const* d_in, const int* in_sizes, int n_in,
                              void* d_out, int out_size) {
    const float* query = (const float*)d_in[0];
    const float* key_  = (const float*)d_in[1];
    const float* value = (const float*)d_in[2];
    const float* Wq = (const float*)d_in[3];
    const float* bq = (const float*)d_in[4];
    const float* Wk = (const float*)d_in[5];
    const float* bk = (const float*)d_in[6];
    const float* Wv = (const float*)d_in[7];
    const float* bv = (const float*)d_in[8];
    const float* Wo = (const float*)d_in[9];
    const float* bo = (const float*)d_in[10];
    float* out = (float*)d_out;

    float *pQ, *pK, *pV, *pO;
    __nv_bfloat16 *pXh, *pXl, *pWh, *pWl;
    cudaGetSymbolAddress((void**)&pQ, g_Q);
    cudaGetSymbolAddress((void**)&pK, g_K);
    cudaGetSymbolAddress((void**)&pV, g_V);
    cudaGetSymbolAddress((void**)&pO, g_O);
    cudaGetSymbolAddress((void**)&pXh, g_Xh);
    cudaGetSymbolAddress((void**)&pXl, g_Xl);
    cudaGetSymbolAddress((void**)&pWh, g_Wh);
    cudaGetSymbolAddress((void**)&pWl, g_Wl);

    cudaFuncSetAttribute(gemm_mma,
                         cudaFuncAttributeMaxDynamicSharedMemorySize, SMEM_GEMM);
    cudaFuncSetAttribute(flash_attn_kernel,
                         cudaFuncAttributeMaxDynamicSharedMemorySize, SMEM_FA);

    // weight transpose + bf16 split (all 4 matrices)
    wsplit_kernel<<<dim3(DIN * DIN / 256, 4), 256>>>(Wq, Wk, Wv, Wo);

    const int splitBlocks = MROWS * DIN / 4 / 256;
    dim3 gg(DIN / 128, MROWS / 128);   // (8, 64)

    split_x_kernel<<<splitBlocks, 256>>>((const float4*)query, pXh, pXl);
    gemm_mma<<<gg, 256, SMEM_GEMM>>>(pXh, pXl, pWh + 0 * DIN * DIN, pWl + 0 * DIN * DIN, bq, pQ);

    split_x_kernel<<<splitBlocks, 256>>>((const float4*)key_, pXh, pXl);
    gemm_mma<<<gg, 256, SMEM_GEMM>>>(pXh, pXl, pWh + 1 * DIN * DIN, pWl + 1 * DIN * DIN, bk, pK);

    split_x_kernel<<<splitBlocks, 256>>>((const float4*)value, pXh, pXl);
    gemm_mma<<<gg, 256, SMEM_GEMM>>>(pXh, pXl, pWh + 2 * DIN * DIN, pWl + 2 * DIN * DIN, bv, pV);

    flash_attn_kernel<<<dim3(SS / 64, HH, BB), 256, SMEM_FA>>>();

    split_x_kernel<<<splitBlocks, 256>>>((const float4*)pO, pXh, pXl);
    gemm_mma<<<gg, 256, SMEM_GEMM>>>(pXh, pXl, pWh + 3 * DIN * DIN, pWl + 3 * DIN * DIN, bo, out);
}

// round 5
// speedup vs baseline: 2.7636x; 2.0464x over previous
#include <cuda_runtime.h>
#include <cuda_bf16.h>
#include <cstdint>

// MultiHeadAttention: B=4, S=2048, D_IN=1024, H=16, D_HEAD=64
// Round 5: flash attention moves to mma.sync bf16 with 2-term splits on both
// QK^T and PV. Projection GEMMs write split bf16 Q/K/V directly; attention
// writes split Oh/Ol consumed by the output GEMM. Final GEMM outputs fp32.

#define BB   4
#define SS   2048
#define DIN  1024
#define HH   16
#define DH   64
#define MROWS (BB * SS)          // 8192

// ---------------- scratch (device globals; no cudaMalloc allowed) -----------
__device__ __nv_bfloat16 g_Xh[MROWS * DIN];     // GEMM A-operand split hi
__device__ __nv_bfloat16 g_Xl[MROWS * DIN];     // GEMM A-operand split lo
__device__ __nv_bfloat16 g_Qh[MROWS * DIN];
__device__ __nv_bfloat16 g_Ql[MROWS * DIN];
__device__ __nv_bfloat16 g_Kh[MROWS * DIN];
__device__ __nv_bfloat16 g_Kl[MROWS * DIN];
__device__ __nv_bfloat16 g_Vh[MROWS * DIN];
__device__ __nv_bfloat16 g_Vl[MROWS * DIN];
__device__ __nv_bfloat16 g_Oh[MROWS * DIN];
__device__ __nv_bfloat16 g_Ol[MROWS * DIN];
__device__ __nv_bfloat16 g_Wh[4][DIN * DIN];    // weights^T split hi ([N,K] k-contig)
__device__ __nv_bfloat16 g_Wl[4][DIN * DIN];    // weights^T split lo

// ============================ mma helpers ====================================
__device__ __forceinline__ uint32_t smem_u32(const void* p) {
    return (uint32_t)__cvta_generic_to_shared((void*)p);
}
__device__ __forceinline__ void ldsm4(uint32_t* r, uint32_t addr) {
    asm volatile("ldmatrix.sync.aligned.m8n8.x4.shared.b16 {%0,%1,%2,%3}, [%4];"
                 : "=r"(r[0]), "=r"(r[1]), "=r"(r[2]), "=r"(r[3]) : "r"(addr));
}
__device__ __forceinline__ void ldsm4t(uint32_t* r, uint32_t addr) {
    asm volatile("ldmatrix.sync.aligned.m8n8.x4.trans.shared.b16 {%0,%1,%2,%3}, [%4];"
                 : "=r"(r[0]), "=r"(r[1]), "=r"(r[2]), "=r"(r[3]) : "r"(addr));
}
__device__ __forceinline__ void mma16816(float* d, const uint32_t* a, const uint32_t* b) {
    asm volatile(
        "mma.sync.aligned.m16n8k16.row.col.f32.bf16.bf16.f32 "
        "{%0,%1,%2,%3}, {%4,%5,%6,%7}, {%8,%9}, {%0,%1,%2,%3};"
        : "+f"(d[0]), "+f"(d[1]), "+f"(d[2]), "+f"(d[3])
        : "r"(a[0]), "r"(a[1]), "r"(a[2]), "r"(a[3]), "r"(b[0]), "r"(b[1]));
}
__device__ __forceinline__ uint32_t packbf(float lo, float hi) {
    __nv_bfloat16 l = __float2bfloat16(lo), h = __float2bfloat16(hi);
    uint16_t lu = *(uint16_t*)&l, hu = *(uint16_t*)&h;
    return (uint32_t)lu | ((uint32_t)hu << 16);
}

// ====================== fp32 -> bf16 split converters ========================
__global__ void split_x_kernel(const float4* __restrict__ X,
                               __nv_bfloat16* __restrict__ Xh,
                               __nv_bfloat16* __restrict__ Xl) {
    long i = (long)blockIdx.x * 256 + threadIdx.x;       // over MROWS*DIN/4
    float4 v = X[i];
    float xs[4] = {v.x, v.y, v.z, v.w};
    __nv_bfloat16 h[4], l[4];
#pragma unroll
    for (int j = 0; j < 4; j++) {
        h[j] = __float2bfloat16(xs[j]);
        l[j] = __float2bfloat16(xs[j] - __bfloat162float(h[j]));
    }
    *(uint2*)(Xh + i * 4) = *(uint2*)h;
    *(uint2*)(Xl + i * 4) = *(uint2*)l;
}

// weights: produce B operand layout [N=1024 rows, K=1024 cols] k-contiguous.
// m=0..2: B[n][k] = Wsrc[h, k, d] with n = h*64+d; m=3: B[n][k] = Wo[k, n]
__global__ void wsplit_kernel(const float* __restrict__ Wq,
                              const float* __restrict__ Wk,
                              const float* __restrict__ Wv,
                              const float* __restrict__ Wo) {
    int m = blockIdx.y;
    int idx = blockIdx.x * 256 + threadIdx.x;   // n*1024 + k
    int k = idx & 1023;
    int n = idx >> 10;
    float x;
    if (m < 3) {
        const float* W = (m == 0) ? Wq : (m == 1) ? Wk : Wv;
        int h = n >> 6, d = n & 63;
        x = W[((long)h * DIN + k) * DH + d];
    } else {
        x = Wo[(long)k * DIN + n];
    }
    __nv_bfloat16 hi = __float2bfloat16(x);
    g_Wh[m][idx] = hi;
    g_Wl[m][idx] = __float2bfloat16(x - __bfloat162float(hi));
}

// ============== mma.sync GEMM: C = (Ah+Al)(Bh+Bl)^T + bias ===================
// BM=128, BN=128, KC=32. 256 threads = 8 warps (2x4), warp tile 64x32.
// SPLIT_OUT=true: write bf16 hi/lo pair arrays; else fp32 C.
#define KC    32
#define ASTR  40
#define TILE_UNITS (128 * ASTR)            // 5120 bf16 per tile
#define STAGE_UNITS (4 * TILE_UNITS)       // 20480
#define SMEM_GEMM (2 * STAGE_UNITS * 2)    // 81920 bytes

__device__ __forceinline__ void load_tile4(__nv_bfloat16* smem, int stage,
                                           const __nv_bfloat16* const* srcs,
                                           int k0, int t) {
#pragma unroll
    for (int w = 0; w < 4; w++) {
        __nv_bfloat16* dst = smem + stage * STAGE_UNITS + w * TILE_UNITS;
        const __nv_bfloat16* src = srcs[w] + k0;
#pragma unroll
        for (int i = 0; i < 4; i++) {
            int u = t + 256 * i;          // 0..1023 (128 rows x 8 uint2)
            int r = u >> 3;
            int c = u & 7;
            *(uint2*)(dst + r * ASTR + c * 4) =
                *(const uint2*)(src + (long)r * DIN + c * 4);
        }
    }
}

template <bool SPLIT_OUT>
__global__ __launch_bounds__(256) void gemm_mma(
    const __nv_bfloat16* __restrict__ Ah, const __nv_bfloat16* __restrict__ Al,
    const __nv_bfloat16* __restrict__ Bh, const __nv_bfloat16* __restrict__ Bl,
    const float* __restrict__ bias, float* __restrict__ C,
    __nv_bfloat16* __restrict__ Ch, __nv_bfloat16* __restrict__ Cl)
{
    extern __shared__ __nv_bfloat16 smem[];
    const uint32_t sb = smem_u32(smem);
    const int t = threadIdx.x, wid = t >> 5, lane = t & 31;
    const int m0 = blockIdx.y * 128, n0 = blockIdx.x * 128;
    const int wm = (wid >> 2) * 64;       // warp m offset (0 or 64)
    const int wn = (wid & 3) * 32;        // warp n offset

    const int a_r  = (lane & 7) + ((lane >> 3) & 1) * 8;
    const int a_kk = (lane >> 4) * 8;
    const int b_n  = (lane & 7) + (lane >> 4) * 8;
    const int b_kk = ((lane >> 3) & 1) * 8;

    const __nv_bfloat16* srcs[4] = {
        Ah + (long)m0 * DIN, Al + (long)m0 * DIN,
        Bh + (long)n0 * DIN, Bl + (long)n0 * DIN };

    float acc[4][4][4];
#pragma unroll
    for (int i = 0; i < 4; i++)
#pragma unroll
        for (int j = 0; j < 4; j++)
#pragma unroll
            for (int e = 0; e < 4; e++) acc[i][j][e] = 0.f;

    load_tile4(smem, 0, srcs, 0, t);
    __syncthreads();

    const int NC = DIN / KC;   // 32
    for (int c = 0; c < NC; c++) {
        const int cur = c & 1;
        if (c + 1 < NC) load_tile4(smem, 1 - cur, srcs, (c + 1) * KC, t);

        const uint32_t stage_b = sb + cur * (STAGE_UNITS * 2);
#pragma unroll
        for (int ks = 0; ks < 2; ks++) {
            uint32_t ah[4][4], al[4][4], bh[2][4], bl[2][4];
#pragma unroll
            for (int mf = 0; mf < 4; mf++) {
                uint32_t off = (uint32_t)((wm + mf * 16 + a_r) * ASTR + ks * 16 + a_kk) * 2;
                ldsm4(ah[mf], stage_b + off);
                ldsm4(al[mf], stage_b + TILE_UNITS * 2 + off);
            }
#pragma unroll
            for (int nf2 = 0; nf2 < 2; nf2++) {
                uint32_t off = (uint32_t)((wn + nf2 * 16 + b_n) * ASTR + ks * 16 + b_kk) * 2;
                ldsm4(bh[nf2], stage_b + TILE_UNITS * 4 + off);
                ldsm4(bl[nf2], stage_b + TILE_UNITS * 6 + off);
            }
#pragma unroll
            for (int mf = 0; mf < 4; mf++)
#pragma unroll
                for (int nf = 0; nf < 4; nf++) {
                    const uint32_t* bhf = &bh[nf >> 1][(nf & 1) * 2];
                    const uint32_t* blf = &bl[nf >> 1][(nf & 1) * 2];
                    mma16816(acc[mf][nf], ah[mf], bhf);
                    mma16816(acc[mf][nf], ah[mf], blf);
                    mma16816(acc[mf][nf], al[mf], bhf);
                }
        }
        __syncthreads();
    }

    // epilogue
    const int em = lane >> 2;
    const int en = (lane & 3) * 2;
#pragma unroll
    for (int mf = 0; mf < 4; mf++) {
#pragma unroll
        for (int half = 0; half < 2; half++) {
            long row = m0 + wm + mf * 16 + em + half * 8;
#pragma unroll
            for (int nf = 0; nf < 4; nf++) {
                int col = n0 + wn + nf * 8 + en;
                float v0 = acc[mf][nf][half * 2 + 0] + bias[col + 0];
                float v1 = acc[mf][nf][half * 2 + 1] + bias[col + 1];
                if (SPLIT_OUT) {
                    __nv_bfloat16 h0 = __float2bfloat16(v0);
                    __nv_bfloat16 h1 = __float2bfloat16(v1);
                    float r0 = v0 - __bfloat162float(h0);
                    float r1 = v1 - __bfloat162float(h1);
                    uint16_t h0u = *(uint16_t*)&h0, h1u = *(uint16_t*)&h1;
                    *(uint32_t*)(Ch + row * DIN + col) =
                        (uint32_t)h0u | ((uint32_t)h1u << 16);
                    *(uint32_t*)(Cl + row * DIN + col) = packbf(r0, r1);
                } else {
                    float2 v; v.x = v0; v.y = v1;
                    *(float2*)(C + row * DIN + col) = v;
                }
            }
        }
    }
}

// ================= flash attention with mma.sync + bf16 splits ===============
// Grid (S/128, H, B), 256 threads = 8 warps; warp owns 16 q-rows x full chunk.
// KV chunk = 64. Smem: Qh,Ql (128x72) + Kh,Kl,Vh,Vl (64x72), stride 72 bf16.
#define AST 72
#define FA_Q_UNITS (128 * AST)             // 9216
#define FA_KV_UNITS (64 * AST)             // 4608
#define SMEM_FA ((2 * FA_Q_UNITS + 4 * FA_KV_UNITS) * 2)   // 73728 bytes

__global__ __launch_bounds__(256, 2) void flash_mma_kernel() {
    extern __shared__ __nv_bfloat16 sm[];
    const uint32_t sb = smem_u32(sm);
    const int t = threadIdx.x, warp = t >> 5, lane = t & 31;
    const int b = blockIdx.z, h = blockIdx.y;
    const int q0 = blockIdx.x * 128;

    __nv_bfloat16* sQh = sm;
    __nv_bfloat16* sQl = sm + FA_Q_UNITS;
    __nv_bfloat16* sKh = sm + 2 * FA_Q_UNITS;
    __nv_bfloat16* sKl = sKh + FA_KV_UNITS;
    __nv_bfloat16* sVh = sKl + FA_KV_UNITS;
    __nv_bfloat16* sVl = sVh + FA_KV_UNITS;
    const uint32_t bQh = sb;
    const uint32_t bQl = sb + FA_Q_UNITS * 2;
    const uint32_t bKh = sb + 2 * FA_Q_UNITS * 2;
    const uint32_t bKl = bKh + FA_KV_UNITS * 2;
    const uint32_t bVh = bKl + FA_KV_UNITS * 2;
    const uint32_t bVl = bVh + FA_KV_UNITS * 2;

    const int a_r  = (lane & 7) + ((lane >> 3) & 1) * 8;
    const int a_kk = (lane >> 4) * 8;
    const int b_n  = (lane & 7) + (lane >> 4) * 8;
    const int b_kk = ((lane >> 3) & 1) * 8;
    const int v_kv = (lane & 7) + ((lane >> 3) & 1) * 8;
    const int v_d  = (lane >> 4) * 8;

    // load Q tile (hi+lo)
    {
        long base = (long)(b * SS + q0) * DIN + h * DH;
#pragma unroll
        for (int i = 0; i < 4; i++) {
            int u = t + 256 * i;
            int r = u >> 3, c = u & 7;
            *(uint4*)(sQh + r * AST + c * 8) = *(const uint4*)(g_Qh + base + (long)r * DIN + c * 8);
            *(uint4*)(sQl + r * AST + c * 8) = *(const uint4*)(g_Ql + base + (long)r * DIN + c * 8);
        }
    }

    float oacc[8][4];
#pragma unroll
    for (int i = 0; i < 8; i++)
#pragma unroll
        for (int j = 0; j < 4; j++) oacc[i][j] = 0.f;
    float m0 = -1e30f, m1 = -1e30f, sl0 = 0.f, sl1 = 0.f;

    for (int kb = 0; kb < SS / 64; kb++) {
        __syncthreads();
        {
            long base = (long)(b * SS + kb * 64) * DIN + h * DH;
#pragma unroll
            for (int i = 0; i < 8; i++) {
                int u = t + 256 * i;
                int w = u >> 9, rem = u & 511;
                int r = rem >> 3, c = rem & 7;
                const __nv_bfloat16* gsrc = (w == 0) ? g_Kh : (w == 1) ? g_Kl : (w == 2) ? g_Vh : g_Vl;
                __nv_bfloat16* dst = (w == 0) ? sKh : (w == 1) ? sKl : (w == 2) ? sVh : sVl;
                *(uint4*)(dst + r * AST + c * 8) = *(const uint4*)(gsrc + base + (long)r * DIN + c * 8);
            }
        }
        __syncthreads();

        // ---- QK^T (split): sacc[nf][e], nf over 8 n8-blocks of 64 kv
        float sacc[8][4];
#pragma unroll
        for (int i = 0; i < 8; i++)
#pragma unroll
            for (int j = 0; j < 4; j++) sacc[i][j] = 0.f;

#pragma unroll
        for (int ks = 0; ks < 4; ks++) {
            uint32_t ah[4], al[4];
            uint32_t qoff = (uint32_t)((warp * 16 + a_r) * AST + ks * 16 + a_kk) * 2;
            ldsm4(ah, bQh + qoff);
            ldsm4(al, bQl + qoff);
#pragma unroll
            for (int g = 0; g < 4; g++) {
                uint32_t kh4[4], kl4[4];
                uint32_t koff = (uint32_t)((g * 16 + b_n) * AST + ks * 16 + b_kk) * 2;
                ldsm4(kh4, bKh + koff);
                ldsm4(kl4, bKl + koff);
                mma16816(sacc[g * 2],     ah, kh4);
                mma16816(sacc[g * 2],     ah, kl4);
                mma16816(sacc[g * 2],     al, kh4);
                mma16816(sacc[g * 2 + 1], ah, kh4 + 2);
                mma16816(sacc[g * 2 + 1], ah, kl4 + 2);
                mma16816(sacc[g * 2 + 1], al, kh4 + 2);
            }
        }

        // ---- online softmax (scale 0.125), rows r0=lane>>2, r1=r0+8
        float mx0 = -1e30f, mx1 = -1e30f;
#pragma unroll
        for (int nf = 0; nf < 8; nf++) {
#pragma unroll
            for (int e = 0; e < 4; e++) sacc[nf][e] *= 0.125f;
            mx0 = fmaxf(mx0, fmaxf(sacc[nf][0], sacc[nf][1]));
            mx1 = fmaxf(mx1, fmaxf(sacc[nf][2], sacc[nf][3]));
        }
        mx0 = fmaxf(mx0, __shfl_xor_sync(0xffffffffu, mx0, 1));
        mx0 = fmaxf(mx0, __shfl_xor_sync(0xffffffffu, mx0, 2));
        mx1 = fmaxf(mx1, __shfl_xor_sync(0xffffffffu, mx1, 1));
        mx1 = fmaxf(mx1, __shfl_xor_sync(0xffffffffu, mx1, 2));

        float nm0 = fmaxf(m0, mx0), nm1 = fmaxf(m1, mx1);
        float al0 = __expf(m0 - nm0), al1 = __expf(m1 - nm1);
        float rs0 = 0.f, rs1 = 0.f;
#pragma unroll
        for (int nf = 0; nf < 8; nf++) {
            sacc[nf][0] = __expf(sacc[nf][0] - nm0);
            sacc[nf][1] = __expf(sacc[nf][1] - nm0);
            sacc[nf][2] = __expf(sacc[nf][2] - nm1);
            sacc[nf][3] = __expf(sacc[nf][3] - nm1);
            rs0 += sacc[nf][0] + sacc[nf][1];
            rs1 += sacc[nf][2] + sacc[nf][3];
        }
        rs0 += __shfl_xor_sync(0xffffffffu, rs0, 1);
        rs0 += __shfl_xor_sync(0xffffffffu, rs0, 2);
        rs1 += __shfl_xor_sync(0xffffffffu, rs1, 1);
        rs1 += __shfl_xor_sync(0xffffffffu, rs1, 2);
        sl0 = sl0 * al0 + rs0;  m0 = nm0;
        sl1 = sl1 * al1 + rs1;  m1 = nm1;
#pragma unroll
        for (int gd = 0; gd < 8; gd++) {
            oacc[gd][0] *= al0;  oacc[gd][1] *= al0;
            oacc[gd][2] *= al1;  oacc[gd][3] *= al1;
        }

        // ---- P -> bf16 A-fragments (hi + residual lo)
        uint32_t ph[4][4], pl[4][4];
#pragma unroll
        for (int ks = 0; ks < 4; ks++) {
#pragma unroll
            for (int q = 0; q < 2; q++) {            // q=0: block 2ks, q=1: 2ks+1
                int nf = 2 * ks + q;
#pragma unroll
                for (int hf = 0; hf < 2; hf++) {     // hf=0: rows r0 (c0,c1); hf=1: r1 (c2,c3)
                    float p0 = sacc[nf][hf * 2 + 0];
                    float p1 = sacc[nf][hf * 2 + 1];
                    __nv_bfloat16 b0 = __float2bfloat16(p0);
                    __nv_bfloat16 b1 = __float2bfloat16(p1);
                    float r0 = p0 - __bfloat162float(b0);
                    float r1 = p1 - __bfloat162float(b1);
                    uint16_t b0u = *(uint16_t*)&b0, b1u = *(uint16_t*)&b1;
                    ph[ks][q * 2 + hf] = (uint32_t)b0u | ((uint32_t)b1u << 16);
                    pl[ks][q * 2 + hf] = packbf(r0, r1);
                }
            }
        }

        // ---- PV (split): oacc[gd] over 8 d8-blocks
#pragma unroll
        for (int ks = 0; ks < 4; ks++) {
#pragma unroll
            for (int g = 0; g < 4; g++) {
                uint32_t vh4[4], vl4[4];
                uint32_t voff = (uint32_t)((ks * 16 + v_kv) * AST + g * 16 + v_d) * 2;
                ldsm4t(vh4, bVh + voff);
                ldsm4t(vl4, bVl + voff);
                mma16816(oacc[g * 2],     ph[ks], vh4);
                mma16816(oacc[g * 2],     ph[ks], vl4);
                mma16816(oacc[g * 2],     pl[ks], vh4);
                mma16816(oacc[g * 2 + 1], ph[ks], vh4 + 2);
                mma16816(oacc[g * 2 + 1], ph[ks], vl4 + 2);
                mma16816(oacc[g * 2 + 1], pl[ks], vh4 + 2);
            }
        }
    }

    // ---- epilogue: normalize, split to bf16 hi/lo, write [row][h*64+d]
    float inv0 = 1.f / sl0, inv1 = 1.f / sl1;
    long row0 = (long)(b * SS + q0 + warp * 16 + (lane >> 2));
    int colb = h * DH + (lane & 3) * 2;
#pragma unroll
    for (int gd = 0; gd < 8; gd++) {
        int col = colb + gd * 8;
        {
            float v0 = oacc[gd][0] * inv0, v1 = oacc[gd][1] * inv0;
            __nv_bfloat16 h0 = __float2bfloat16(v0), h1 = __float2bfloat16(v1);
            uint16_t h0u = *(uint16_t*)&h0, h1u = *(uint16_t*)&h1;
            *(uint32_t*)(g_Oh + row0 * DIN + col) = (uint32_t)h0u | ((uint32_t)h1u << 16);
            *(uint32_t*)(g_Ol + row0 * DIN + col) =
                packbf(v0 - __bfloat162float(h0), v1 - __bfloat162float(h1));
        }
        {
            float v0 = oacc[gd][2] * inv1, v1 = oacc[gd][3] * inv1;
            __nv_bfloat16 h0 = __float2bfloat16(v0), h1 = __float2bfloat16(v1);
            uint16_t h0u = *(uint16_t*)&h0, h1u = *(uint16_t*)&h1;
            *(uint32_t*)(g_Oh + (row0 + 8) * DIN + col) = (uint32_t)h0u | ((uint32_t)h1u << 16);
            *(uint32_t*)(g_Ol + (row0 + 8) * DIN + col) =
                packbf(v0 - __bfloat162float(h0), v1 - __bfloat162float(h1));
        }
    }
}

// ---------------- launcher ---------------------------------------------------
extern "C" void kernel_launch(void* const* d_in, const int* in_sizes, int n_in,
                              void* d_out, int out_size) {
    const float* query = (const float*)d_in[0];
    const float* key_  = (const float*)d_in[1];
    const float* value = (const float*)d_in[2];
    const float* Wq = (const float*)d_in[3];
    const float* bq = (const float*)d_in[4];
    const float* Wk = (const float*)d_in[5];
    const float* bk = (const float*)d_in[6];
    const float* Wv = (const float*)d_in[7];
    const float* bv = (const float*)d_in[8];
    const float* Wo = (const float*)d_in[9];
    const float* bo = (const float*)d_in[10];
    float* out = (float*)d_out;

    __nv_bfloat16 *pXh, *pXl, *pWh, *pWl, *pQh, *pQl, *pKh, *pKl, *pVh, *pVl, *pOh, *pOl;
    cudaGetSymbolAddress((void**)&pXh, g_Xh);
    cudaGetSymbolAddress((void**)&pXl, g_Xl);
    cudaGetSymbolAddress((void**)&pWh, g_Wh);
    cudaGetSymbolAddress((void**)&pWl, g_Wl);
    cudaGetSymbolAddress((void**)&pQh, g_Qh);
    cudaGetSymbolAddress((void**)&pQl, g_Ql);
    cudaGetSymbolAddress((void**)&pKh, g_Kh);
    cudaGetSymbolAddress((void**)&pKl, g_Kl);
    cudaGetSymbolAddress((void**)&pVh, g_Vh);
    cudaGetSymbolAddress((void**)&pVl, g_Vl);
    cudaGetSymbolAddress((void**)&pOh, g_Oh);
    cudaGetSymbolAddress((void**)&pOl, g_Ol);

    cudaFuncSetAttribute(gemm_mma<true>,
                         cudaFuncAttributeMaxDynamicSharedMemorySize, SMEM_GEMM);
    cudaFuncSetAttribute(gemm_mma<false>,
                         cudaFuncAttributeMaxDynamicSharedMemorySize, SMEM_GEMM);
    cudaFuncSetAttribute(flash_mma_kernel,
                         cudaFuncAttributeMaxDynamicSharedMemorySize, SMEM_FA);

    wsplit_kernel<<<dim3(DIN * DIN / 256, 4), 256>>>(Wq, Wk, Wv, Wo);

    const int splitBlocks = MROWS * DIN / 4 / 256;
    dim3 gg(DIN / 128, MROWS / 128);   // (8, 64)

    split_x_kernel<<<splitBlocks, 256>>>((const float4*)query, pXh, pXl);
    gemm_mma<true><<<gg, 256, SMEM_GEMM>>>(pXh, pXl, pWh + 0 * DIN * DIN, pWl + 0 * DIN * DIN,
                                           bq, nullptr, pQh, pQl);

    split_x_kernel<<<splitBlocks, 256>>>((const float4*)key_, pXh, pXl);
    gemm_mma<true><<<gg, 256, SMEM_GEMM>>>(pXh, pXl, pWh + 1 * DIN * DIN, pWl + 1 * DIN * DIN,
                                           bk, nullptr, pKh, pKl);

    split_x_kernel<<<splitBlocks, 256>>>((const float4*)value, pXh, pXl);
    gemm_mma<true><<<gg, 256, SMEM_GEMM>>>(pXh, pXl, pWh + 2 * DIN * DIN, pWl + 2 * DIN * DIN,
                                           bv, nullptr, pVh, pVl);

    flash_mma_kernel<<<dim3(SS / 128, HH, BB), 256, SMEM_FA>>>();

    gemm_mma<false><<<gg, 256, SMEM_GEMM>>>(pOh, pOl, pWh + 3 * DIN * DIN, pWl + 3 * DIN * DIN,
                                            bo, out, nullptr, nullptr);
}

// round 8
// speedup vs baseline: 3.0320x; 1.0971x over previous
#include <cuda_runtime.h>
#include <cuda_bf16.h>
#include <cstdint>

// MultiHeadAttention: B=4, S=2048, D_IN=1024, H=16, D_HEAD=64
// Round 8 (= round 7 resubmitted after infra failure): cp.async double-buffer
// pipelines in gemm_mma and flash_mma; flash KV copy-loop geometry fixed
// (rows are 8x16B chunks — half-loaded K caused the round-6 NaN).

#define BB   4
#define SS   2048
#define DIN  1024
#define HH   16
#define DH   64
#define MROWS (BB * SS)          // 8192

// ---------------- scratch (device globals; no cudaMalloc allowed) -----------
__device__ __nv_bfloat16 g_Xh[MROWS * DIN];
__device__ __nv_bfloat16 g_Xl[MROWS * DIN];
__device__ __nv_bfloat16 g_Qh[MROWS * DIN];
__device__ __nv_bfloat16 g_Ql[MROWS * DIN];
__device__ __nv_bfloat16 g_Kh[MROWS * DIN];
__device__ __nv_bfloat16 g_Kl[MROWS * DIN];
__device__ __nv_bfloat16 g_Vh[MROWS * DIN];
__device__ __nv_bfloat16 g_Vl[MROWS * DIN];
__device__ __nv_bfloat16 g_Oh[MROWS * DIN];
__device__ __nv_bfloat16 g_Ol[MROWS * DIN];
__device__ __nv_bfloat16 g_Wh[4][DIN * DIN];
__device__ __nv_bfloat16 g_Wl[4][DIN * DIN];

// ============================ asm helpers ====================================
__device__ __forceinline__ uint32_t smem_u32(const void* p) {
    return (uint32_t)__cvta_generic_to_shared((void*)p);
}
__device__ __forceinline__ void ldsm4(uint32_t* r, uint32_t addr) {
    asm volatile("ldmatrix.sync.aligned.m8n8.x4.shared.b16 {%0,%1,%2,%3}, [%4];"
                 : "=r"(r[0]), "=r"(r[1]), "=r"(r[2]), "=r"(r[3]) : "r"(addr));
}
__device__ __forceinline__ void ldsm4t(uint32_t* r, uint32_t addr) {
    asm volatile("ldmatrix.sync.aligned.m8n8.x4.trans.shared.b16 {%0,%1,%2,%3}, [%4];"
                 : "=r"(r[0]), "=r"(r[1]), "=r"(r[2]), "=r"(r[3]) : "r"(addr));
}
__device__ __forceinline__ void mma16816(float* d, const uint32_t* a, const uint32_t* b) {
    asm volatile(
        "mma.sync.aligned.m16n8k16.row.col.f32.bf16.bf16.f32 "
        "{%0,%1,%2,%3}, {%4,%5,%6,%7}, {%8,%9}, {%0,%1,%2,%3};"
        : "+f"(d[0]), "+f"(d[1]), "+f"(d[2]), "+f"(d[3])
        : "r"(a[0]), "r"(a[1]), "r"(a[2]), "r"(a[3]), "r"(b[0]), "r"(b[1]));
}
__device__ __forceinline__ void cp16(uint32_t dst, const void* src) {
    asm volatile("cp.async.cg.shared.global [%0], [%1], 16;"
                 :: "r"(dst), "l"(src) : "memory");
}
#define CP_COMMIT() asm volatile("cp.async.commit_group;" ::: "memory")
#define CP_WAIT0()  asm volatile("cp.async.wait_group 0;" ::: "memory")
__device__ __forceinline__ uint32_t packbf(float lo, float hi) {
    __nv_bfloat16 l = __float2bfloat16(lo), h = __float2bfloat16(hi);
    uint16_t lu = *(uint16_t*)&l, hu = *(uint16_t*)&h;
    return (uint32_t)lu | ((uint32_t)hu << 16);
}

// ====================== fp32 -> bf16 split converters ========================
__global__ void split_x_kernel(const float4* __restrict__ X,
                               __nv_bfloat16* __restrict__ Xh,
                               __nv_bfloat16* __restrict__ Xl) {
    long i = (long)blockIdx.x * 256 + threadIdx.x;
    float4 v = X[i];
    float xs[4] = {v.x, v.y, v.z, v.w};
    __nv_bfloat16 h[4], l[4];
#pragma unroll
    for (int j = 0; j < 4; j++) {
        h[j] = __float2bfloat16(xs[j]);
        l[j] = __float2bfloat16(xs[j] - __bfloat162float(h[j]));
    }
    *(uint2*)(Xh + i * 4) = *(uint2*)h;
    *(uint2*)(Xl + i * 4) = *(uint2*)l;
}

__global__ void wsplit_kernel(const float* __restrict__ Wq,
                              const float* __restrict__ Wk,
                              const float* __restrict__ Wv,
                              const float* __restrict__ Wo) {
    int m = blockIdx.y;
    int idx = blockIdx.x * 256 + threadIdx.x;   // n*1024 + k
    int k = idx & 1023;
    int n = idx >> 10;
    float x;
    if (m < 3) {
        const float* W = (m == 0) ? Wq : (m == 1) ? Wk : Wv;
        int h = n >> 6, d = n & 63;
        x = W[((long)h * DIN + k) * DH + d];
    } else {
        x = Wo[(long)k * DIN + n];
    }
    __nv_bfloat16 hi = __float2bfloat16(x);
    g_Wh[m][idx] = hi;
    g_Wl[m][idx] = __float2bfloat16(x - __bfloat162float(hi));
}

// ============== mma.sync GEMM (cp.async pipelined) ===========================
#define KC    32
#define ASTR  40
#define TILE_UNITS (128 * ASTR)            // 5120 bf16
#define STAGE_UNITS (4 * TILE_UNITS)       // 20480
#define SMEM_GEMM (2 * STAGE_UNITS * 2)    // 81920 bytes

__device__ __forceinline__ void issue_tile4(uint32_t sb, int stage,
                                            const __nv_bfloat16* const* srcs,
                                            int k0, int t) {
#pragma unroll
    for (int i = 0; i < 8; i++) {
        int u = t + 256 * i;            // 0..2047: 4 tiles x 128 rows x 4 chunks
        int w = u >> 9;
        int rem = u & 511;
        int r = rem >> 2;
        int c = rem & 3;
        uint32_t dst = sb + (uint32_t)(stage * STAGE_UNITS + w * TILE_UNITS
                                       + r * ASTR + c * 8) * 2;
        cp16(dst, srcs[w] + k0 + (long)r * DIN + c * 8);
    }
}

template <bool SPLIT_OUT>
__global__ __launch_bounds__(256) void gemm_mma(
    const __nv_bfloat16* __restrict__ Ah, const __nv_bfloat16* __restrict__ Al,
    const __nv_bfloat16* __restrict__ Bh, const __nv_bfloat16* __restrict__ Bl,
    const float* __restrict__ bias, float* __restrict__ C,
    __nv_bfloat16* __restrict__ Ch, __nv_bfloat16* __restrict__ Cl)
{
    extern __shared__ __nv_bfloat16 smem[];
    const uint32_t sb = smem_u32(smem);
    const int t = threadIdx.x, wid = t >> 5, lane = t & 31;
    const int m0 = blockIdx.y * 128, n0 = blockIdx.x * 128;
    const int wm = (wid >> 2) * 64;
    const int wn = (wid & 3) * 32;

    const int a_r  = (lane & 7) + ((lane >> 3) & 1) * 8;
    const int a_kk = (lane >> 4) * 8;
    const int b_n  = (lane & 7) + (lane >> 4) * 8;
    const int b_kk = ((lane >> 3) & 1) * 8;

    const __nv_bfloat16* srcs[4] = {
        Ah + (long)m0 * DIN, Al + (long)m0 * DIN,
        Bh + (long)n0 * DIN, Bl + (long)n0 * DIN };

    float acc[4][4][4];
#pragma unroll
    for (int i = 0; i < 4; i++)
#pragma unroll
        for (int j = 0; j < 4; j++)
#pragma unroll
            for (int e = 0; e < 4; e++) acc[i][j][e] = 0.f;

    issue_tile4(sb, 0, srcs, 0, t);
    CP_COMMIT();

    const int NC = DIN / KC;   // 32
    for (int c = 0; c < NC; c++) {
        const int cur = c & 1;
        CP_WAIT0();
        __syncthreads();          // stage `cur` visible; prev compute done
        if (c + 1 < NC) {
            issue_tile4(sb, 1 - cur, srcs, (c + 1) * KC, t);
            CP_COMMIT();
        }

        const uint32_t stage_b = sb + cur * (STAGE_UNITS * 2);
#pragma unroll
        for (int ks = 0; ks < 2; ks++) {
            uint32_t ah[4][4], al[4][4], bh[2][4], bl[2][4];
#pragma unroll
            for (int mf = 0; mf < 4; mf++) {
                uint32_t off = (uint32_t)((wm + mf * 16 + a_r) * ASTR + ks * 16 + a_kk) * 2;
                ldsm4(ah[mf], stage_b + off);
                ldsm4(al[mf], stage_b + TILE_UNITS * 2 + off);
            }
#pragma unroll
            for (int nf2 = 0; nf2 < 2; nf2++) {
                uint32_t off = (uint32_t)((wn + nf2 * 16 + b_n) * ASTR + ks * 16 + b_kk) * 2;
                ldsm4(bh[nf2], stage_b + TILE_UNITS * 4 + off);
                ldsm4(bl[nf2], stage_b + TILE_UNITS * 6 + off);
            }
#pragma unroll
            for (int mf = 0; mf < 4; mf++)
#pragma unroll
                for (int nf = 0; nf < 4; nf++) {
                    const uint32_t* bhf = &bh[nf >> 1][(nf & 1) * 2];
                    const uint32_t* blf = &bl[nf >> 1][(nf & 1) * 2];
                    mma16816(acc[mf][nf], ah[mf], bhf);
                    mma16816(acc[mf][nf], ah[mf], blf);
                    mma16816(acc[mf][nf], al[mf], bhf);
                }
        }
    }

    const int em = lane >> 2;
    const int en = (lane & 3) * 2;
#pragma unroll
    for (int mf = 0; mf < 4; mf++) {
#pragma unroll
        for (int half = 0; half < 2; half++) {
            long row = m0 + wm + mf * 16 + em + half * 8;
#pragma unroll
            for (int nf = 0; nf < 4; nf++) {
                int col = n0 + wn + nf * 8 + en;
                float v0 = acc[mf][nf][half * 2 + 0] + bias[col + 0];
                float v1 = acc[mf][nf][half * 2 + 1] + bias[col + 1];
                if (SPLIT_OUT) {
                    __nv_bfloat16 h0 = __float2bfloat16(v0);
                    __nv_bfloat16 h1 = __float2bfloat16(v1);
                    uint16_t h0u = *(uint16_t*)&h0, h1u = *(uint16_t*)&h1;
                    *(uint32_t*)(Ch + row * DIN + col) =
                        (uint32_t)h0u | ((uint32_t)h1u << 16);
                    *(uint32_t*)(Cl + row * DIN + col) =
                        packbf(v0 - __bfloat162float(h0), v1 - __bfloat162float(h1));
                } else {
                    float2 v; v.x = v0; v.y = v1;
                    *(float2*)(C + row * DIN + col) = v;
                }
            }
        }
    }
}

// ============ flash attention (mma.sync, cp.async double-buffered KV) ========
#define AST 72
#define FA_Q_UNITS (128 * AST)             // 9216
#define FA_KV_TILE (64 * AST)              // 4608
#define FA_STAGE_UNITS (4 * FA_KV_TILE)    // 18432
#define SMEM_FA ((2 * FA_Q_UNITS + 2 * FA_STAGE_UNITS) * 2)   // 110592 bytes

// KV chunk issue: 4 tiles x 64 rows x 8 chunks(16B) = 2048 cp.async ops.
__device__ __forceinline__ void issue_kv(uint32_t dbase,
                                         const __nv_bfloat16* const* gkv,
                                         long off, int t) {
#pragma unroll
    for (int i = 0; i < 8; i++) {
        int u = t + 256 * i;            // 0..2047
        int w = u >> 9;
        int rem = u & 511;
        int r = rem >> 3;               // 0..63
        int c = rem & 7;                // 0..7 (8 x 16B = full 128B row)
        uint32_t dst = dbase + (uint32_t)(w * FA_KV_TILE + r * AST + c * 8) * 2;
        cp16(dst, gkv[w] + off + (long)r * DIN + c * 8);
    }
}

__global__ __launch_bounds__(256, 2) void flash_mma_kernel() {
    extern __shared__ __nv_bfloat16 sm[];
    const uint32_t sb = smem_u32(sm);
    const int t = threadIdx.x, warp = t >> 5, lane = t & 31;
    const int b = blockIdx.z, h = blockIdx.y;
    const int q0 = blockIdx.x * 128;

    __nv_bfloat16* sQh = sm;
    __nv_bfloat16* sQl = sm + FA_Q_UNITS;
    const uint32_t bQh = sb;
    const uint32_t bQl = sb + FA_Q_UNITS * 2;
    const uint32_t bKV = sb + 2 * FA_Q_UNITS * 2;   // stage0 base (bytes)

    const int a_r  = (lane & 7) + ((lane >> 3) & 1) * 8;
    const int a_kk = (lane >> 4) * 8;
    const int b_n  = (lane & 7) + (lane >> 4) * 8;
    const int b_kk = ((lane >> 3) & 1) * 8;
    const int v_kv = (lane & 7) + ((lane >> 3) & 1) * 8;
    const int v_d  = (lane >> 4) * 8;

    const long kvbase0 = (long)(b * SS) * DIN + h * DH;
    const __nv_bfloat16* gkv[4];
    gkv[0] = g_Kh + kvbase0; gkv[1] = g_Kl + kvbase0;
    gkv[2] = g_Vh + kvbase0; gkv[3] = g_Vl + kvbase0;

    // issue KV chunk 0 into stage 0
    issue_kv(bKV, gkv, 0, t);
    CP_COMMIT();

    // load Q tile (plain; visible after first __syncthreads)
    {
        long base = (long)(b * SS + q0) * DIN + h * DH;
#pragma unroll
        for (int i = 0; i < 4; i++) {
            int u = t + 256 * i;
            int r = u >> 3, c = u & 7;
            *(uint4*)(sQh + r * AST + c * 8) = *(const uint4*)(g_Qh + base + (long)r * DIN + c * 8);
            *(uint4*)(sQl + r * AST + c * 8) = *(const uint4*)(g_Ql + base + (long)r * DIN + c * 8);
        }
    }

    float oacc[8][4];
#pragma unroll
    for (int i = 0; i < 8; i++)
#pragma unroll
        for (int j = 0; j < 4; j++) oacc[i][j] = 0.f;
    float m0 = -1e30f, m1 = -1e30f, sl0 = 0.f, sl1 = 0.f;

    const int NKB = SS / 64;
    for (int kb = 0; kb < NKB; kb++) {
        const int cur = kb & 1;
        CP_WAIT0();
        __syncthreads();        // stage `cur` visible; prev compute done
        if (kb + 1 < NKB) {
            issue_kv(bKV + (uint32_t)((1 - cur) * FA_STAGE_UNITS) * 2,
                     gkv, (long)(kb + 1) * 64 * DIN, t);
            CP_COMMIT();
        }

        const uint32_t bKh = bKV + (uint32_t)(cur * FA_STAGE_UNITS) * 2;
        const uint32_t bKl = bKh + FA_KV_TILE * 2;
        const uint32_t bVh = bKl + FA_KV_TILE * 2;
        const uint32_t bVl = bVh + FA_KV_TILE * 2;

        // ---- QK^T (split)
        float sacc[8][4];
#pragma unroll
        for (int i = 0; i < 8; i++)
#pragma unroll
            for (int j = 0; j < 4; j++) sacc[i][j] = 0.f;

#pragma unroll
        for (int ks = 0; ks < 4; ks++) {
            uint32_t ah[4], al[4];
            uint32_t qoff = (uint32_t)((warp * 16 + a_r) * AST + ks * 16 + a_kk) * 2;
            ldsm4(ah, bQh + qoff);
            ldsm4(al, bQl + qoff);
#pragma unroll
            for (int g = 0; g < 4; g++) {
                uint32_t kh4[4], kl4[4];
                uint32_t koff = (uint32_t)((g * 16 + b_n) * AST + ks * 16 + b_kk) * 2;
                ldsm4(kh4, bKh + koff);
                ldsm4(kl4, bKl + koff);
                mma16816(sacc[g * 2],     ah, kh4);
                mma16816(sacc[g * 2],     ah, kl4);
                mma16816(sacc[g * 2],     al, kh4);
                mma16816(sacc[g * 2 + 1], ah, kh4 + 2);
                mma16816(sacc[g * 2 + 1], ah, kl4 + 2);
                mma16816(sacc[g * 2 + 1], al, kh4 + 2);
            }
        }

        // ---- online softmax (scale 0.125)
        float mx0 = -1e30f, mx1 = -1e30f;
#pragma unroll
        for (int nf = 0; nf < 8; nf++) {
#pragma unroll
            for (int e = 0; e < 4; e++) sacc[nf][e] *= 0.125f;
            mx0 = fmaxf(mx0, fmaxf(sacc[nf][0], sacc[nf][1]));
            mx1 = fmaxf(mx1, fmaxf(sacc[nf][2], sacc[nf][3]));
        }
        mx0 = fmaxf(mx0, __shfl_xor_sync(0xffffffffu, mx0, 1));
        mx0 = fmaxf(mx0, __shfl_xor_sync(0xffffffffu, mx0, 2));
        mx1 = fmaxf(mx1, __shfl_xor_sync(0xffffffffu, mx1, 1));
        mx1 = fmaxf(mx1, __shfl_xor_sync(0xffffffffu, mx1, 2));

        float nm0 = fmaxf(m0, mx0), nm1 = fmaxf(m1, mx1);
        float al0 = __expf(m0 - nm0), al1 = __expf(m1 - nm1);
        float rs0 = 0.f, rs1 = 0.f;
#pragma unroll
        for (int nf = 0; nf < 8; nf++) {
            sacc[nf][0] = __expf(sacc[nf][0] - nm0);
            sacc[nf][1] = __expf(sacc[nf][1] - nm0);
            sacc[nf][2] = __expf(sacc[nf][2] - nm1);
            sacc[nf][3] = __expf(sacc[nf][3] - nm1);
            rs0 += sacc[nf][0] + sacc[nf][1];
            rs1 += sacc[nf][2] + sacc[nf][3];
        }
        rs0 += __shfl_xor_sync(0xffffffffu, rs0, 1);
        rs0 += __shfl_xor_sync(0xffffffffu, rs0, 2);
        rs1 += __shfl_xor_sync(0xffffffffu, rs1, 1);
        rs1 += __shfl_xor_sync(0xffffffffu, rs1, 2);
        sl0 = sl0 * al0 + rs0;  m0 = nm0;
        sl1 = sl1 * al1 + rs1;  m1 = nm1;
#pragma unroll
        for (int gd = 0; gd < 8; gd++) {
            oacc[gd][0] *= al0;  oacc[gd][1] *= al0;
            oacc[gd][2] *= al1;  oacc[gd][3] *= al1;
        }

        // ---- P -> bf16 A-fragments (hi + residual lo)
        uint32_t ph[4][4], pl[4][4];
#pragma unroll
        for (int ks = 0; ks < 4; ks++) {
#pragma unroll
            for (int q = 0; q < 2; q++) {
                int nf = 2 * ks + q;
#pragma unroll
                for (int hf = 0; hf < 2; hf++) {
                    float p0 = sacc[nf][hf * 2 + 0];
                    float p1 = sacc[nf][hf * 2 + 1];
                    __nv_bfloat16 b0 = __float2bfloat16(p0);
                    __nv_bfloat16 b1 = __float2bfloat16(p1);
                    uint16_t b0u = *(uint16_t*)&b0, b1u = *(uint16_t*)&b1;
                    ph[ks][q * 2 + hf] = (uint32_t)b0u | ((uint32_t)b1u << 16);
                    pl[ks][q * 2 + hf] = packbf(p0 - __bfloat162float(b0),
                                                p1 - __bfloat162float(b1));
                }
            }
        }

        // ---- PV (split)
#pragma unroll
        for (int ks = 0; ks < 4; ks++) {
#pragma unroll
            for (int g = 0; g < 4; g++) {
                uint32_t vh4[4], vl4[4];
                uint32_t voff = (uint32_t)((ks * 16 + v_kv) * AST + g * 16 + v_d) * 2;
                ldsm4t(vh4, bVh + voff);
                ldsm4t(vl4, bVl + voff);
                mma16816(oacc[g * 2],     ph[ks], vh4);
                mma16816(oacc[g * 2],     ph[ks], vl4);
                mma16816(oacc[g * 2],     pl[ks], vh4);
                mma16816(oacc[g * 2 + 1], ph[ks], vh4 + 2);
                mma16816(oacc[g * 2 + 1], ph[ks], vl4 + 2);
                mma16816(oacc[g * 2 + 1], pl[ks], vh4 + 2);
            }
        }
    }

    // ---- epilogue: normalize, split, write [row][h*64+d]
    float inv0 = 1.f / sl0, inv1 = 1.f / sl1;
    long row0 = (long)(b * SS + q0 + warp * 16 + (lane >> 2));
    int colb = h * DH + (lane & 3) * 2;
#pragma unroll
    for (int gd = 0; gd < 8; gd++) {
        int col = colb + gd * 8;
        {
            float v0 = oacc[gd][0] * inv0, v1 = oacc[gd][1] * inv0;
            __nv_bfloat16 h0 = __float2bfloat16(v0), h1 = __float2bfloat16(v1);
            uint16_t h0u = *(uint16_t*)&h0, h1u = *(uint16_t*)&h1;
            *(uint32_t*)(g_Oh + row0 * DIN + col) = (uint32_t)h0u | ((uint32_t)h1u << 16);
            *(uint32_t*)(g_Ol + row0 * DIN + col) =
                packbf(v0 - __bfloat162float(h0), v1 - __bfloat162float(h1));
        }
        {
            float v0 = oacc[gd][2] * inv1, v1 = oacc[gd][3] * inv1;
            __nv_bfloat16 h0 = __float2bfloat16(v0), h1 = __float2bfloat16(v1);
            uint16_t h0u = *(uint16_t*)&h0, h1u = *(uint16_t*)&h1;
            *(uint32_t*)(g_Oh + (row0 + 8) * DIN + col) = (uint32_t)h0u | ((uint32_t)h1u << 16);
            *(uint32_t*)(g_Ol + (row0 + 8) * DIN + col) =
                packbf(v0 - __bfloat162float(h0), v1 - __bfloat162float(h1));
        }
    }
}

// ---------------- launcher ---------------------------------------------------
extern "C" void kernel_launch(void* const* d_in, const int* in_sizes, int n_in,
                              void* d_out, int out_size) {
    const float* query = (const float*)d_in[0];
    const float* key_  = (const float*)d_in[1];
    const float* value = (const float*)d_in[2];
    const float* Wq = (const float*)d_in[3];
    const float* bq = (const float*)d_in[4];
    const float* Wk = (const float*)d_in[5];
    const float* bk = (const float*)d_in[6];
    const float* Wv = (const float*)d_in[7];
    const float* bv = (const float*)d_in[8];
    const float* Wo = (const float*)d_in[9];
    const float* bo = (const float*)d_in[10];
    float* out = (float*)d_out;

    __nv_bfloat16 *pXh, *pXl, *pWh, *pWl, *pQh, *pQl, *pKh, *pKl, *pVh, *pVl, *pOh, *pOl;
    cudaGetSymbolAddress((void**)&pXh, g_Xh);
    cudaGetSymbolAddress((void**)&pXl, g_Xl);
    cudaGetSymbolAddress((void**)&pWh, g_Wh);
    cudaGetSymbolAddress((void**)&pWl, g_Wl);
    cudaGetSymbolAddress((void**)&pQh, g_Qh);
    cudaGetSymbolAddress((void**)&pQl, g_Ql);
    cudaGetSymbolAddress((void**)&pKh, g_Kh);
    cudaGetSymbolAddress((void**)&pKl, g_Kl);
    cudaGetSymbolAddress((void**)&pVh, g_Vh);
    cudaGetSymbolAddress((void**)&pVl, g_Vl);
    cudaGetSymbolAddress((void**)&pOh, g_Oh);
    cudaGetSymbolAddress((void**)&pOl, g_Ol);

    cudaFuncSetAttribute(gemm_mma<true>,
                         cudaFuncAttributeMaxDynamicSharedMemorySize, SMEM_GEMM);
    cudaFuncSetAttribute(gemm_mma<false>,
                         cudaFuncAttributeMaxDynamicSharedMemorySize, SMEM_GEMM);
    cudaFuncSetAttribute(flash_mma_kernel,
                         cudaFuncAttributeMaxDynamicSharedMemorySize, SMEM_FA);

    wsplit_kernel<<<dim3(DIN * DIN / 256, 4), 256>>>(Wq, Wk, Wv, Wo);

    const int splitBlocks = MROWS * DIN / 4 / 256;
    dim3 gg(DIN / 128, MROWS / 128);   // (8, 64)

    split_x_kernel<<<splitBlocks, 256>>>((const float4*)query, pXh, pXl);
    gemm_mma<true><<<gg, 256, SMEM_GEMM>>>(pXh, pXl, pWh + 0 * DIN * DIN, pWl + 0 * DIN * DIN,
                                           bq, nullptr, pQh, pQl);

    split_x_kernel<<<splitBlocks, 256>>>((const float4*)key_, pXh, pXl);
    gemm_mma<true><<<gg, 256, SMEM_GEMM>>>(pXh, pXl, pWh + 1 * DIN * DIN, pWl + 1 * DIN * DIN,
                                           bk, nullptr, pKh, pKl);

    split_x_kernel<<<splitBlocks, 256>>>((const float4*)value, pXh, pXl);
    gemm_mma<true><<<gg, 256, SMEM_GEMM>>>(pXh, pXl, pWh + 2 * DIN * DIN, pWl + 2 * DIN * DIN,
                                           bv, nullptr, pVh, pVl);

    flash_mma_kernel<<<dim3(SS / 128, HH, BB), 256, SMEM_FA>>>();

    gemm_mma<false><<<gg, 256, SMEM_GEMM>>>(pOh, pOl, pWh + 3 * DIN * DIN, pWl + 3 * DIN * DIN,
                                            bo, out, nullptr, nullptr);
}

// round 10
// speedup vs baseline: 3.1696x; 1.0454x over previous
#include <cuda_runtime.h>
#include <cuda_bf16.h>
#include <cstdint>

// MultiHeadAttention: B=4, S=2048, D_IN=1024, H=16, D_HEAD=64
// Round 10 (= round 9 resubmitted after infra failure): batch QKV projections
// into one launch (tail-wave smoothing), batch the 3 split_x passes, fold the
// 0.125 softmax scale into Wq/bq.

#define BB   4
#define SS   2048
#define DIN  1024
#define HH   16
#define DH   64
#define MROWS (BB * SS)          // 8192
#define XSZ  (MROWS * DIN)

// ---------------- scratch (device globals; no cudaMalloc allowed) -----------
__device__ __nv_bfloat16 g_Xh[3][XSZ];          // split activations (q,k,v inputs)
__device__ __nv_bfloat16 g_Xl[3][XSZ];
__device__ __nv_bfloat16 g_Qh[XSZ];
__device__ __nv_bfloat16 g_Ql[XSZ];
__device__ __nv_bfloat16 g_Kh[XSZ];
__device__ __nv_bfloat16 g_Kl[XSZ];
__device__ __nv_bfloat16 g_Vh[XSZ];
__device__ __nv_bfloat16 g_Vl[XSZ];
__device__ __nv_bfloat16 g_Oh[XSZ];
__device__ __nv_bfloat16 g_Ol[XSZ];
__device__ __nv_bfloat16 g_Wh[4][DIN * DIN];
__device__ __nv_bfloat16 g_Wl[4][DIN * DIN];

// ============================ asm helpers ====================================
__device__ __forceinline__ uint32_t smem_u32(const void* p) {
    return (uint32_t)__cvta_generic_to_shared((void*)p);
}
__device__ __forceinline__ void ldsm4(uint32_t* r, uint32_t addr) {
    asm volatile("ldmatrix.sync.aligned.m8n8.x4.shared.b16 {%0,%1,%2,%3}, [%4];"
                 : "=r"(r[0]), "=r"(r[1]), "=r"(r[2]), "=r"(r[3]) : "r"(addr));
}
__device__ __forceinline__ void ldsm4t(uint32_t* r, uint32_t addr) {
    asm volatile("ldmatrix.sync.aligned.m8n8.x4.trans.shared.b16 {%0,%1,%2,%3}, [%4];"
                 : "=r"(r[0]), "=r"(r[1]), "=r"(r[2]), "=r"(r[3]) : "r"(addr));
}
__device__ __forceinline__ void mma16816(float* d, const uint32_t* a, const uint32_t* b) {
    asm volatile(
        "mma.sync.aligned.m16n8k16.row.col.f32.bf16.bf16.f32 "
        "{%0,%1,%2,%3}, {%4,%5,%6,%7}, {%8,%9}, {%0,%1,%2,%3};"
        : "+f"(d[0]), "+f"(d[1]), "+f"(d[2]), "+f"(d[3])
        : "r"(a[0]), "r"(a[1]), "r"(a[2]), "r"(a[3]), "r"(b[0]), "r"(b[1]));
}
__device__ __forceinline__ void cp16(uint32_t dst, const void* src) {
    asm volatile("cp.async.cg.shared.global [%0], [%1], 16;"
                 :: "r"(dst), "l"(src) : "memory");
}
#define CP_COMMIT() asm volatile("cp.async.commit_group;" ::: "memory")
#define CP_WAIT0()  asm volatile("cp.async.wait_group 0;" ::: "memory")
__device__ __forceinline__ uint32_t packbf(float lo, float hi) {
    __nv_bfloat16 l = __float2bfloat16(lo), h = __float2bfloat16(hi);
    uint16_t lu = *(uint16_t*)&l, hu = *(uint16_t*)&h;
    return (uint32_t)lu | ((uint32_t)hu << 16);
}

// ====================== fp32 -> bf16 split converters ========================
// batched over 3 inputs: grid (XSZ/4/256, 3)
__global__ void split3_kernel(const float4* __restrict__ X0,
                              const float4* __restrict__ X1,
                              const float4* __restrict__ X2) {
    int z = blockIdx.y;
    const float4* X = (z == 0) ? X0 : (z == 1) ? X1 : X2;
    long i = (long)blockIdx.x * 256 + threadIdx.x;
    float4 v = X[i];
    float xs[4] = {v.x, v.y, v.z, v.w};
    __nv_bfloat16 h[4], l[4];
#pragma unroll
    for (int j = 0; j < 4; j++) {
        h[j] = __float2bfloat16(xs[j]);
        l[j] = __float2bfloat16(xs[j] - __bfloat162float(h[j]));
    }
    *(uint2*)(&g_Xh[z][i * 4]) = *(uint2*)h;
    *(uint2*)(&g_Xl[z][i * 4]) = *(uint2*)l;
}

// weights: B layout [N=1024 rows, K=1024 cols] k-contiguous.
// m=0 (Wq) is pre-scaled by 0.125 (folds the 1/sqrt(64) softmax scale).
__global__ void wsplit_kernel(const float* __restrict__ Wq,
                              const float* __restrict__ Wk,
                              const float* __restrict__ Wv,
                              const float* __restrict__ Wo) {
    int m = blockIdx.y;
    int idx = blockIdx.x * 256 + threadIdx.x;   // n*1024 + k
    int k = idx & 1023;
    int n = idx >> 10;
    float x;
    if (m < 3) {
        const float* W = (m == 0) ? Wq : (m == 1) ? Wk : Wv;
        int h = n >> 6, d = n & 63;
        x = W[((long)h * DIN + k) * DH + d];
        if (m == 0) x *= 0.125f;
    } else {
        x = Wo[(long)k * DIN + n];
    }
    __nv_bfloat16 hi = __float2bfloat16(x);
    g_Wh[m][idx] = hi;
    g_Wl[m][idx] = __float2bfloat16(x - __bfloat162float(hi));
}

// ============== mma.sync GEMM core (cp.async pipelined) ======================
#define KC    32
#define ASTR  40
#define TILE_UNITS (128 * ASTR)            // 5120 bf16
#define STAGE_UNITS (4 * TILE_UNITS)       // 20480
#define SMEM_GEMM (2 * STAGE_UNITS * 2)    // 81920 bytes

__device__ __forceinline__ void issue_tile4(uint32_t sb, int stage,
                                            const __nv_bfloat16* const* srcs,
                                            int k0, int t) {
#pragma unroll
    for (int i = 0; i < 8; i++) {
        int u = t + 256 * i;            // 0..2047: 4 tiles x 128 rows x 4 chunks
        int w = u >> 9;
        int rem = u & 511;
        int r = rem >> 2;
        int c = rem & 3;
        uint32_t dst = sb + (uint32_t)(stage * STAGE_UNITS + w * TILE_UNITS
                                       + r * ASTR + c * 8) * 2;
        cp16(dst, srcs[w] + k0 + (long)r * DIN + c * 8);
    }
}

// Core mainloop: accumulates the 128x128 tile into acc[4][4][4].
__device__ __forceinline__ void gemm_core(
    uint32_t sb, const __nv_bfloat16* const* srcs, float acc[4][4][4],
    int t, int wid, int lane)
{
    const int wm = (wid >> 2) * 64;
    const int wn = (wid & 3) * 32;
    const int a_r  = (lane & 7) + ((lane >> 3) & 1) * 8;
    const int a_kk = (lane >> 4) * 8;
    const int b_n  = (lane & 7) + (lane >> 4) * 8;
    const int b_kk = ((lane >> 3) & 1) * 8;

    issue_tile4(sb, 0, srcs, 0, t);
    CP_COMMIT();

    const int NC = DIN / KC;   // 32
    for (int c = 0; c < NC; c++) {
        const int cur = c & 1;
        CP_WAIT0();
        __syncthreads();          // stage `cur` visible; prev compute done
        if (c + 1 < NC) {
            issue_tile4(sb, 1 - cur, srcs, (c + 1) * KC, t);
            CP_COMMIT();
        }

        const uint32_t stage_b = sb + cur * (STAGE_UNITS * 2);
#pragma unroll
        for (int ks = 0; ks < 2; ks++) {
            uint32_t ah[4][4], al[4][4], bh[2][4], bl[2][4];
#pragma unroll
            for (int mf = 0; mf < 4; mf++) {
                uint32_t off = (uint32_t)((wm + mf * 16 + a_r) * ASTR + ks * 16 + a_kk) * 2;
                ldsm4(ah[mf], stage_b + off);
                ldsm4(al[mf], stage_b + TILE_UNITS * 2 + off);
            }
#pragma unroll
            for (int nf2 = 0; nf2 < 2; nf2++) {
                uint32_t off = (uint32_t)((wn + nf2 * 16 + b_n) * ASTR + ks * 16 + b_kk) * 2;
                ldsm4(bh[nf2], stage_b + TILE_UNITS * 4 + off);
                ldsm4(bl[nf2], stage_b + TILE_UNITS * 6 + off);
            }
#pragma unroll
            for (int mf = 0; mf < 4; mf++)
#pragma unroll
                for (int nf = 0; nf < 4; nf++) {
                    const uint32_t* bhf = &bh[nf >> 1][(nf & 1) * 2];
                    const uint32_t* blf = &bl[nf >> 1][(nf & 1) * 2];
                    mma16816(acc[mf][nf], ah[mf], bhf);
                    mma16816(acc[mf][nf], ah[mf], blf);
                    mma16816(acc[mf][nf], al[mf], bhf);
                }
        }
    }
}

// Batched QKV projection: grid (8, 64, 3); z selects input/weight/bias/output.
__global__ __launch_bounds__(256) void gemm_qkv(
    const float* __restrict__ bq, const float* __restrict__ bk,
    const float* __restrict__ bv)
{
    extern __shared__ __nv_bfloat16 smem[];
    const uint32_t sb = smem_u32(smem);
    const int t = threadIdx.x, wid = t >> 5, lane = t & 31;
    const int m0 = blockIdx.y * 128, n0 = blockIdx.x * 128;
    const int z = blockIdx.z;

    const float* bias = (z == 0) ? bq : (z == 1) ? bk : bv;
    __nv_bfloat16* Ch = (z == 0) ? g_Qh : (z == 1) ? g_Kh : g_Vh;
    __nv_bfloat16* Cl = (z == 0) ? g_Ql : (z == 1) ? g_Kl : g_Vl;
    const float bscale = (z == 0) ? 0.125f : 1.0f;

    const __nv_bfloat16* srcs[4] = {
        &g_Xh[z][(long)m0 * DIN], &g_Xl[z][(long)m0 * DIN],
        &g_Wh[z][(long)n0 * DIN], &g_Wl[z][(long)n0 * DIN] };

    float acc[4][4][4];
#pragma unroll
    for (int i = 0; i < 4; i++)
#pragma unroll
        for (int j = 0; j < 4; j++)
#pragma unroll
            for (int e = 0; e < 4; e++) acc[i][j][e] = 0.f;

    gemm_core(sb, srcs, acc, t, wid, lane);

    const int wm = (wid >> 2) * 64;
    const int wn = (wid & 3) * 32;
    const int em = lane >> 2;
    const int en = (lane & 3) * 2;
#pragma unroll
    for (int mf = 0; mf < 4; mf++) {
#pragma unroll
        for (int half = 0; half < 2; half++) {
            long row = m0 + wm + mf * 16 + em + half * 8;
#pragma unroll
            for (int nf = 0; nf < 4; nf++) {
                int col = n0 + wn + nf * 8 + en;
                float v0 = acc[mf][nf][half * 2 + 0] + bias[col + 0] * bscale;
                float v1 = acc[mf][nf][half * 2 + 1] + bias[col + 1] * bscale;
                __nv_bfloat16 h0 = __float2bfloat16(v0);
                __nv_bfloat16 h1 = __float2bfloat16(v1);
                uint16_t h0u = *(uint16_t*)&h0, h1u = *(uint16_t*)&h1;
                *(uint32_t*)(Ch + row * DIN + col) =
                    (uint32_t)h0u | ((uint32_t)h1u << 16);
                *(uint32_t*)(Cl + row * DIN + col) =
                    packbf(v0 - __bfloat162float(h0), v1 - __bfloat162float(h1));
            }
        }
    }
}

// Output projection: fp32 result to d_out.
__global__ __launch_bounds__(256) void gemm_out(
    const __nv_bfloat16* __restrict__ Ah, const __nv_bfloat16* __restrict__ Al,
    const __nv_bfloat16* __restrict__ Bh, const __nv_bfloat16* __restrict__ Bl,
    const float* __restrict__ bias, float* __restrict__ C)
{
    extern __shared__ __nv_bfloat16 smem[];
    const uint32_t sb = smem_u32(smem);
    const int t = threadIdx.x, wid = t >> 5, lane = t & 31;
    const int m0 = blockIdx.y * 128, n0 = blockIdx.x * 128;

    const __nv_bfloat16* srcs[4] = {
        Ah + (long)m0 * DIN, Al + (long)m0 * DIN,
        Bh + (long)n0 * DIN, Bl + (long)n0 * DIN };

    float acc[4][4][4];
#pragma unroll
    for (int i = 0; i < 4; i++)
#pragma unroll
        for (int j = 0; j < 4; j++)
#pragma unroll
            for (int e = 0; e < 4; e++) acc[i][j][e] = 0.f;

    gemm_core(sb, srcs, acc, t, wid, lane);

    const int wm = (wid >> 2) * 64;
    const int wn = (wid & 3) * 32;
    const int em = lane >> 2;
    const int en = (lane & 3) * 2;
#pragma unroll
    for (int mf = 0; mf < 4; mf++) {
#pragma unroll
        for (int half = 0; half < 2; half++) {
            long row = m0 + wm + mf * 16 + em + half * 8;
#pragma unroll
            for (int nf = 0; nf < 4; nf++) {
                int col = n0 + wn + nf * 8 + en;
                float2 v;
                v.x = acc[mf][nf][half * 2 + 0] + bias[col + 0];
                v.y = acc[mf][nf][half * 2 + 1] + bias[col + 1];
                *(float2*)(C + row * DIN + col) = v;
            }
        }
    }
}

// ============ flash attention (mma.sync, cp.async double-buffered KV) ========
// Scores arrive pre-scaled (0.125 folded into Wq/bq).
#define AST 72
#define FA_Q_UNITS (128 * AST)             // 9216
#define FA_KV_TILE (64 * AST)              // 4608
#define FA_STAGE_UNITS (4 * FA_KV_TILE)    // 18432
#define SMEM_FA ((2 * FA_Q_UNITS + 2 * FA_STAGE_UNITS) * 2)   // 110592 bytes

// KV chunk issue: 4 tiles x 64 rows x 8 chunks(16B) = 2048 cp.async ops.
__device__ __forceinline__ void issue_kv(uint32_t dbase,
                                         const __nv_bfloat16* const* gkv,
                                         long off, int t) {
#pragma unroll
    for (int i = 0; i < 8; i++) {
        int u = t + 256 * i;            // 0..2047
        int w = u >> 9;
        int rem = u & 511;
        int r = rem >> 3;               // 0..63
        int c = rem & 7;                // 0..7 (8 x 16B = full 128B row)
        uint32_t dst = dbase + (uint32_t)(w * FA_KV_TILE + r * AST + c * 8) * 2;
        cp16(dst, gkv[w] + off + (long)r * DIN + c * 8);
    }
}

__global__ __launch_bounds__(256, 2) void flash_mma_kernel() {
    extern __shared__ __nv_bfloat16 sm[];
    const uint32_t sb = smem_u32(sm);
    const int t = threadIdx.x, warp = t >> 5, lane = t & 31;
    const int b = blockIdx.z, h = blockIdx.y;
    const int q0 = blockIdx.x * 128;

    __nv_bfloat16* sQh = sm;
    __nv_bfloat16* sQl = sm + FA_Q_UNITS;
    const uint32_t bQh = sb;
    const uint32_t bQl = sb + FA_Q_UNITS * 2;
    const uint32_t bKV = sb + 2 * FA_Q_UNITS * 2;   // stage0 base (bytes)

    const int a_r  = (lane & 7) + ((lane >> 3) & 1) * 8;
    const int a_kk = (lane >> 4) * 8;
    const int b_n  = (lane & 7) + (lane >> 4) * 8;
    const int b_kk = ((lane >> 3) & 1) * 8;
    const int v_kv = (lane & 7) + ((lane >> 3) & 1) * 8;
    const int v_d  = (lane >> 4) * 8;

    const long kvbase0 = (long)(b * SS) * DIN + h * DH;
    const __nv_bfloat16* gkv[4];
    gkv[0] = g_Kh + kvbase0; gkv[1] = g_Kl + kvbase0;
    gkv[2] = g_Vh + kvbase0; gkv[3] = g_Vl + kvbase0;

    issue_kv(bKV, gkv, 0, t);
    CP_COMMIT();

    {
        long base = (long)(b * SS + q0) * DIN + h * DH;
#pragma unroll
        for (int i = 0; i < 4; i++) {
            int u = t + 256 * i;
            int r = u >> 3, c = u & 7;
            *(uint4*)(sQh + r * AST + c * 8) = *(const uint4*)(g_Qh + base + (long)r * DIN + c * 8);
            *(uint4*)(sQl + r * AST + c * 8) = *(const uint4*)(g_Ql + base + (long)r * DIN + c * 8);
        }
    }

    float oacc[8][4];
#pragma unroll
    for (int i = 0; i < 8; i++)
#pragma unroll
        for (int j = 0; j < 4; j++) oacc[i][j] = 0.f;
    float m0 = -1e30f, m1 = -1e30f, sl0 = 0.f, sl1 = 0.f;

    const int NKB = SS / 64;
    for (int kb = 0; kb < NKB; kb++) {
        const int cur = kb & 1;
        CP_WAIT0();
        __syncthreads();
        if (kb + 1 < NKB) {
            issue_kv(bKV + (uint32_t)((1 - cur) * FA_STAGE_UNITS) * 2,
                     gkv, (long)(kb + 1) * 64 * DIN, t);
            CP_COMMIT();
        }

        const uint32_t bKh = bKV + (uint32_t)(cur * FA_STAGE_UNITS) * 2;
        const uint32_t bKl = bKh + FA_KV_TILE * 2;
        const uint32_t bVh = bKl + FA_KV_TILE * 2;
        const uint32_t bVl = bVh + FA_KV_TILE * 2;

        // ---- QK^T (split); scores already scaled
        float sacc[8][4];
#pragma unroll
        for (int i = 0; i < 8; i++)
#pragma unroll
            for (int j = 0; j < 4; j++) sacc[i][j] = 0.f;

#pragma unroll
        for (int ks = 0; ks < 4; ks++) {
            uint32_t ah[4], al[4];
            uint32_t qoff = (uint32_t)((warp * 16 + a_r) * AST + ks * 16 + a_kk) * 2;
            ldsm4(ah, bQh + qoff);
            ldsm4(al, bQl + qoff);
#pragma unroll
            for (int g = 0; g < 4; g++) {
                uint32_t kh4[4], kl4[4];
                uint32_t koff = (uint32_t)((g * 16 + b_n) * AST + ks * 16 + b_kk) * 2;
                ldsm4(kh4, bKh + koff);
                ldsm4(kl4, bKl + koff);
                mma16816(sacc[g * 2],     ah, kh4);
                mma16816(sacc[g * 2],     ah, kl4);
                mma16816(sacc[g * 2],     al, kh4);
                mma16816(sacc[g * 2 + 1], ah, kh4 + 2);
                mma16816(sacc[g * 2 + 1], ah, kl4 + 2);
                mma16816(sacc[g * 2 + 1], al, kh4 + 2);
            }
        }

        // ---- online softmax
        float mx0 = -1e30f, mx1 = -1e30f;
#pragma unroll
        for (int nf = 0; nf < 8; nf++) {
            mx0 = fmaxf(mx0, fmaxf(sacc[nf][0], sacc[nf][1]));
            mx1 = fmaxf(mx1, fmaxf(sacc[nf][2], sacc[nf][3]));
        }
        mx0 = fmaxf(mx0, __shfl_xor_sync(0xffffffffu, mx0, 1));
        mx0 = fmaxf(mx0, __shfl_xor_sync(0xffffffffu, mx0, 2));
        mx1 = fmaxf(mx1, __shfl_xor_sync(0xffffffffu, mx1, 1));
        mx1 = fmaxf(mx1, __shfl_xor_sync(0xffffffffu, mx1, 2));

        float nm0 = fmaxf(m0, mx0), nm1 = fmaxf(m1, mx1);
        float al0 = __expf(m0 - nm0), al1 = __expf(m1 - nm1);
        float rs0 = 0.f, rs1 = 0.f;
#pragma unroll
        for (int nf = 0; nf < 8; nf++) {
            sacc[nf][0] = __expf(sacc[nf][0] - nm0);
            sacc[nf][1] = __expf(sacc[nf][1] - nm0);
            sacc[nf][2] = __expf(sacc[nf][2] - nm1);
            sacc[nf][3] = __expf(sacc[nf][3] - nm1);
            rs0 += sacc[nf][0] + sacc[nf][1];
            rs1 += sacc[nf][2] + sacc[nf][3];
        }
        rs0 += __shfl_xor_sync(0xffffffffu, rs0, 1);
        rs0 += __shfl_xor_sync(0xffffffffu, rs0, 2);
        rs1 += __shfl_xor_sync(0xffffffffu, rs1, 1);
        rs1 += __shfl_xor_sync(0xffffffffu, rs1, 2);
        sl0 = sl0 * al0 + rs0;  m0 = nm0;
        sl1 = sl1 * al1 + rs1;  m1 = nm1;
#pragma unroll
        for (int gd = 0; gd < 8; gd++) {
            oacc[gd][0] *= al0;  oacc[gd][1] *= al0;
            oacc[gd][2] *= al1;  oacc[gd][3] *= al1;
        }

        // ---- P -> bf16 A-fragments (hi + residual lo)
        uint32_t ph[4][4], pl[4][4];
#pragma unroll
        for (int ks = 0; ks < 4; ks++) {
#pragma unroll
            for (int q = 0; q < 2; q++) {
                int nf = 2 * ks + q;
#pragma unroll
                for (int hf = 0; hf < 2; hf++) {
                    float p0 = sacc[nf][hf * 2 + 0];
                    float p1 = sacc[nf][hf * 2 + 1];
                    __nv_bfloat16 b0 = __float2bfloat16(p0);
                    __nv_bfloat16 b1 = __float2bfloat16(p1);
                    uint16_t b0u = *(uint16_t*)&b0, b1u = *(uint16_t*)&b1;
                    ph[ks][q * 2 + hf] = (uint32_t)b0u | ((uint32_t)b1u << 16);
                    pl[ks][q * 2 + hf] = packbf(p0 - __bfloat162float(b0),
                                                p1 - __bfloat162float(b1));
                }
            }
        }

        // ---- PV (split)
#pragma unroll
        for (int ks = 0; ks < 4; ks++) {
#pragma unroll
            for (int g = 0; g < 4; g++) {
                uint32_t vh4[4], vl4[4];
                uint32_t voff = (uint32_t)((ks * 16 + v_kv) * AST + g * 16 + v_d) * 2;
                ldsm4t(vh4, bVh + voff);
                ldsm4t(vl4, bVl + voff);
                mma16816(oacc[g * 2],     ph[ks], vh4);
                mma16816(oacc[g * 2],     ph[ks], vl4);
                mma16816(oacc[g * 2],     pl[ks], vh4);
                mma16816(oacc[g * 2 + 1], ph[ks], vh4 + 2);
                mma16816(oacc[g * 2 + 1], ph[ks], vl4 + 2);
                mma16816(oacc[g * 2 + 1], pl[ks], vh4 + 2);
            }
        }
    }

    // ---- epilogue: normalize, split, write [row][h*64+d]
    float inv0 = 1.f / sl0, inv1 = 1.f / sl1;
    long row0 = (long)(b * SS + q0 + warp * 16 + (lane >> 2));
    int colb = h * DH + (lane & 3) * 2;
#pragma unroll
    for (int gd = 0; gd < 8; gd++) {
        int col = colb + gd * 8;
        {
            float v0 = oacc[gd][0] * inv0, v1 = oacc[gd][1] * inv0;
            __nv_bfloat16 h0 = __float2bfloat16(v0), h1 = __float2bfloat16(v1);
            uint16_t h0u = *(uint16_t*)&h0, h1u = *(uint16_t*)&h1;
            *(uint32_t*)(g_Oh + row0 * DIN + col) = (uint32_t)h0u | ((uint32_t)h1u << 16);
            *(uint32_t*)(g_Ol + row0 * DIN + col) =
                packbf(v0 - __bfloat162float(h0), v1 - __bfloat162float(h1));
        }
        {
            float v0 = oacc[gd][2] * inv1, v1 = oacc[gd][3] * inv1;
            __nv_bfloat16 h0 = __float2bfloat16(v0), h1 = __float2bfloat16(v1);
            uint16_t h0u = *(uint16_t*)&h0, h1u = *(uint16_t*)&h1;
            *(uint32_t*)(g_Oh + (row0 + 8) * DIN + col) = (uint32_t)h0u | ((uint32_t)h1u << 16);
            *(uint32_t*)(g_Ol + (row0 + 8) * DIN + col) =
                packbf(v0 - __bfloat162float(h0), v1 - __bfloat162float(h1));
        }
    }
}

// ---------------- launcher ---------------------------------------------------
extern "C" void kernel_launch(void* const* d_in, const int* in_sizes, int n_in,
                              void* d_out, int out_size) {
    const float* query = (const float*)d_in[0];
    const float* key_  = (const float*)d_in[1];
    const float* value = (const float*)d_in[2];
    const float* Wq = (const float*)d_in[3];
    const float* bq = (const float*)d_in[4];
    const float* Wk = (const float*)d_in[5];
    const float* bk = (const float*)d_in[6];
    const float* Wv = (const float*)d_in[7];
    const float* bv = (const float*)d_in[8];
    const float* Wo = (const float*)d_in[9];
    const float* bo = (const float*)d_in[10];
    float* out = (float*)d_out;

    __nv_bfloat16 *pWh, *pWl, *pOh, *pOl;
    cudaGetSymbolAddress((void**)&pWh, g_Wh);
    cudaGetSymbolAddress((void**)&pWl, g_Wl);
    cudaGetSymbolAddress((void**)&pOh, g_Oh);
    cudaGetSymbolAddress((void**)&pOl, g_Ol);

    cudaFuncSetAttribute(gemm_qkv,
                         cudaFuncAttributeMaxDynamicSharedMemorySize, SMEM_GEMM);
    cudaFuncSetAttribute(gemm_out,
                         cudaFuncAttributeMaxDynamicSharedMemorySize, SMEM_GEMM);
    cudaFuncSetAttribute(flash_mma_kernel,
                         cudaFuncAttributeMaxDynamicSharedMemorySize, SMEM_FA);

    wsplit_kernel<<<dim3(DIN * DIN / 256, 4), 256>>>(Wq, Wk, Wv, Wo);

    const int splitBlocks = XSZ / 4 / 256;
    split3_kernel<<<dim3(splitBlocks, 3), 256>>>(
        (const float4*)query, (const float4*)key_, (const float4*)value);

    gemm_qkv<<<dim3(DIN / 128, MROWS / 128, 3), 256, SMEM_GEMM>>>(bq, bk, bv);

    flash_mma_kernel<<<dim3(SS / 128, HH, BB), 256, SMEM_FA>>>();

    gemm_out<<<dim3(DIN / 128, MROWS / 128), 256, SMEM_GEMM>>>(
        pOh, pOl, pWh + 3 * DIN * DIN, pWl + 3 * DIN * DIN, bo, out);
}

// round 11
// speedup vs baseline: 3.1820x; 1.0039x over previous
#include <cuda_runtime.h>
#include <cuda_bf16.h>
#include <cstdint>

// MultiHeadAttention: B=4, S=2048, D_IN=1024, H=16, D_HEAD=64
// Round 11: GEMM register-pressure fix (transient A-fragments +
// __launch_bounds__(256,2) -> 2 CTAs/SM, 4 warps/SMSP) and log2e fold
// (exp2f softmax, scale 0.125*log2e baked into Wq/bq).

#define BB   4
#define SS   2048
#define DIN  1024
#define HH   16
#define DH   64
#define MROWS (BB * SS)          // 8192
#define XSZ  (MROWS * DIN)
#define SCALE_Q 0.18033688011112042f   // 0.125 * log2(e)

// ---------------- scratch (device globals; no cudaMalloc allowed) -----------
__device__ __nv_bfloat16 g_Xh[3][XSZ];
__device__ __nv_bfloat16 g_Xl[3][XSZ];
__device__ __nv_bfloat16 g_Qh[XSZ];
__device__ __nv_bfloat16 g_Ql[XSZ];
__device__ __nv_bfloat16 g_Kh[XSZ];
__device__ __nv_bfloat16 g_Kl[XSZ];
__device__ __nv_bfloat16 g_Vh[XSZ];
__device__ __nv_bfloat16 g_Vl[XSZ];
__device__ __nv_bfloat16 g_Oh[XSZ];
__device__ __nv_bfloat16 g_Ol[XSZ];
__device__ __nv_bfloat16 g_Wh[4][DIN * DIN];
__device__ __nv_bfloat16 g_Wl[4][DIN * DIN];

// ============================ asm helpers ====================================
__device__ __forceinline__ uint32_t smem_u32(const void* p) {
    return (uint32_t)__cvta_generic_to_shared((void*)p);
}
__device__ __forceinline__ void ldsm4(uint32_t* r, uint32_t addr) {
    asm volatile("ldmatrix.sync.aligned.m8n8.x4.shared.b16 {%0,%1,%2,%3}, [%4];"
                 : "=r"(r[0]), "=r"(r[1]), "=r"(r[2]), "=r"(r[3]) : "r"(addr));
}
__device__ __forceinline__ void ldsm4t(uint32_t* r, uint32_t addr) {
    asm volatile("ldmatrix.sync.aligned.m8n8.x4.trans.shared.b16 {%0,%1,%2,%3}, [%4];"
                 : "=r"(r[0]), "=r"(r[1]), "=r"(r[2]), "=r"(r[3]) : "r"(addr));
}
__device__ __forceinline__ void mma16816(float* d, const uint32_t* a, const uint32_t* b) {
    asm volatile(
        "mma.sync.aligned.m16n8k16.row.col.f32.bf16.bf16.f32 "
        "{%0,%1,%2,%3}, {%4,%5,%6,%7}, {%8,%9}, {%0,%1,%2,%3};"
        : "+f"(d[0]), "+f"(d[1]), "+f"(d[2]), "+f"(d[3])
        : "r"(a[0]), "r"(a[1]), "r"(a[2]), "r"(a[3]), "r"(b[0]), "r"(b[1]));
}
__device__ __forceinline__ void cp16(uint32_t dst, const void* src) {
    asm volatile("cp.async.cg.shared.global [%0], [%1], 16;"
                 :: "r"(dst), "l"(src) : "memory");
}
#define CP_COMMIT() asm volatile("cp.async.commit_group;" ::: "memory")
#define CP_WAIT0()  asm volatile("cp.async.wait_group 0;" ::: "memory")
__device__ __forceinline__ uint32_t packbf(float lo, float hi) {
    __nv_bfloat16 l = __float2bfloat16(lo), h = __float2bfloat16(hi);
    uint16_t lu = *(uint16_t*)&l, hu = *(uint16_t*)&h;
    return (uint32_t)lu | ((uint32_t)hu << 16);
}

// ====================== fp32 -> bf16 split converters ========================
__global__ void split3_kernel(const float4* __restrict__ X0,
                              const float4* __restrict__ X1,
                              const float4* __restrict__ X2) {
    int z = blockIdx.y;
    const float4* X = (z == 0) ? X0 : (z == 1) ? X1 : X2;
    long i = (long)blockIdx.x * 256 + threadIdx.x;
    float4 v = X[i];
    float xs[4] = {v.x, v.y, v.z, v.w};
    __nv_bfloat16 h[4], l[4];
#pragma unroll
    for (int j = 0; j < 4; j++) {
        h[j] = __float2bfloat16(xs[j]);
        l[j] = __float2bfloat16(xs[j] - __bfloat162float(h[j]));
    }
    *(uint2*)(&g_Xh[z][i * 4]) = *(uint2*)h;
    *(uint2*)(&g_Xl[z][i * 4]) = *(uint2*)l;
}

// m=0 (Wq) is pre-scaled by SCALE_Q = 0.125*log2(e) (softmax in exp2 domain).
__global__ void wsplit_kernel(const float* __restrict__ Wq,
                              const float* __restrict__ Wk,
                              const float* __restrict__ Wv,
                              const float* __restrict__ Wo) {
    int m = blockIdx.y;
    int idx = blockIdx.x * 256 + threadIdx.x;   // n*1024 + k
    int k = idx & 1023;
    int n = idx >> 10;
    float x;
    if (m < 3) {
        const float* W = (m == 0) ? Wq : (m == 1) ? Wk : Wv;
        int h = n >> 6, d = n & 63;
        x = W[((long)h * DIN + k) * DH + d];
        if (m == 0) x *= SCALE_Q;
    } else {
        x = Wo[(long)k * DIN + n];
    }
    __nv_bfloat16 hi = __float2bfloat16(x);
    g_Wh[m][idx] = hi;
    g_Wl[m][idx] = __float2bfloat16(x - __bfloat162float(hi));
}

// ============== mma.sync GEMM core (cp.async pipelined) ======================
#define KC    32
#define ASTR  40
#define TILE_UNITS (128 * ASTR)            // 5120 bf16
#define STAGE_UNITS (4 * TILE_UNITS)       // 20480
#define SMEM_GEMM (2 * STAGE_UNITS * 2)    // 81920 bytes

__device__ __forceinline__ void issue_tile4(uint32_t sb, int stage,
                                            const __nv_bfloat16* const* srcs,
                                            int k0, int t) {
#pragma unroll
    for (int i = 0; i < 8; i++) {
        int u = t + 256 * i;            // 0..2047: 4 tiles x 128 rows x 4 chunks
        int w = u >> 9;
        int rem = u & 511;
        int r = rem >> 2;
        int c = rem & 3;
        uint32_t dst = sb + (uint32_t)(stage * STAGE_UNITS + w * TILE_UNITS
                                       + r * ASTR + c * 8) * 2;
        cp16(dst, srcs[w] + k0 + (long)r * DIN + c * 8);
    }
}

// Core mainloop: accumulates the 128x128 tile into acc[4][4][4].
// A-fragments are double-buffered (2 live sets) to cut register pressure so
// two 256-thread CTAs fit per SM.
__device__ __forceinline__ void gemm_core(
    uint32_t sb, const __nv_bfloat16* const* srcs, float acc[4][4][4],
    int t, int wid, int lane)
{
    const int wm = (wid >> 2) * 64;
    const int wn = (wid & 3) * 32;
    const int a_r  = (lane & 7) + ((lane >> 3) & 1) * 8;
    const int a_kk = (lane >> 4) * 8;
    const int b_n  = (lane & 7) + (lane >> 4) * 8;
    const int b_kk = ((lane >> 3) & 1) * 8;

    issue_tile4(sb, 0, srcs, 0, t);
    CP_COMMIT();

    const int NC = DIN / KC;   // 32
    for (int c = 0; c < NC; c++) {
        const int cur = c & 1;
        CP_WAIT0();
        __syncthreads();          // stage `cur` visible; prev compute done
        if (c + 1 < NC) {
            issue_tile4(sb, 1 - cur, srcs, (c + 1) * KC, t);
            CP_COMMIT();
        }

        const uint32_t stage_b = sb + cur * (STAGE_UNITS * 2);
#pragma unroll
        for (int ks = 0; ks < 2; ks++) {
            uint32_t bh[2][4], bl[2][4];
#pragma unroll
            for (int nf2 = 0; nf2 < 2; nf2++) {
                uint32_t off = (uint32_t)((wn + nf2 * 16 + b_n) * ASTR + ks * 16 + b_kk) * 2;
                ldsm4(bh[nf2], stage_b + TILE_UNITS * 4 + off);
                ldsm4(bl[nf2], stage_b + TILE_UNITS * 6 + off);
            }
            // A fragments: double-buffered, loaded one mf ahead.
            uint32_t ah[2][4], al[2][4];
            {
                uint32_t off0 = (uint32_t)((wm + a_r) * ASTR + ks * 16 + a_kk) * 2;
                ldsm4(ah[0], stage_b + off0);
                ldsm4(al[0], stage_b + TILE_UNITS * 2 + off0);
            }
#pragma unroll
            for (int mf = 0; mf < 4; mf++) {
                const int curb = mf & 1;
                if (mf < 3) {
                    uint32_t offn = (uint32_t)((wm + (mf + 1) * 16 + a_r) * ASTR
                                               + ks * 16 + a_kk) * 2;
                    ldsm4(ah[1 - curb], stage_b + offn);
                    ldsm4(al[1 - curb], stage_b + TILE_UNITS * 2 + offn);
                }
#pragma unroll
                for (int nf = 0; nf < 4; nf++) {
                    const uint32_t* bhf = &bh[nf >> 1][(nf & 1) * 2];
                    const uint32_t* blf = &bl[nf >> 1][(nf & 1) * 2];
                    mma16816(acc[mf][nf], ah[curb], bhf);
                    mma16816(acc[mf][nf], ah[curb], blf);
                    mma16816(acc[mf][nf], al[curb], bhf);
                }
            }
        }
    }
}

// Batched QKV projection: grid (8, 64, 3); z selects input/weight/bias/output.
__global__ __launch_bounds__(256, 2) void gemm_qkv(
    const float* __restrict__ bq, const float* __restrict__ bk,
    const float* __restrict__ bv)
{
    extern __shared__ __nv_bfloat16 smem[];
    const uint32_t sb = smem_u32(smem);
    const int t = threadIdx.x, wid = t >> 5, lane = t & 31;
    const int m0 = blockIdx.y * 128, n0 = blockIdx.x * 128;
    const int z = blockIdx.z;

    const float* bias = (z == 0) ? bq : (z == 1) ? bk : bv;
    __nv_bfloat16* Ch = (z == 0) ? g_Qh : (z == 1) ? g_Kh : g_Vh;
    __nv_bfloat16* Cl = (z == 0) ? g_Ql : (z == 1) ? g_Kl : g_Vl;
    const float bscale = (z == 0) ? SCALE_Q : 1.0f;

    const __nv_bfloat16* srcs[4] = {
        &g_Xh[z][(long)m0 * DIN], &g_Xl[z][(long)m0 * DIN],
        &g_Wh[z][(long)n0 * DIN], &g_Wl[z][(long)n0 * DIN] };

    float acc[4][4][4];
#pragma unroll
    for (int i = 0; i < 4; i++)
#pragma unroll
        for (int j = 0; j < 4; j++)
#pragma unroll
            for (int e = 0; e < 4; e++) acc[i][j][e] = 0.f;

    gemm_core(sb, srcs, acc, t, wid, lane);

    const int wm = (wid >> 2) * 64;
    const int wn = (wid & 3) * 32;
    const int em = lane >> 2;
    const int en = (lane & 3) * 2;
#pragma unroll
    for (int mf = 0; mf < 4; mf++) {
#pragma unroll
        for (int half = 0; half < 2; half++) {
            long row = m0 + wm + mf * 16 + em + half * 8;
#pragma unroll
            for (int nf = 0; nf < 4; nf++) {
                int col = n0 + wn + nf * 8 + en;
                float v0 = acc[mf][nf][half * 2 + 0] + bias[col + 0] * bscale;
                float v1 = acc[mf][nf][half * 2 + 1] + bias[col + 1] * bscale;
                __nv_bfloat16 h0 = __float2bfloat16(v0);
                __nv_bfloat16 h1 = __float2bfloat16(v1);
                uint16_t h0u = *(uint16_t*)&h0, h1u = *(uint16_t*)&h1;
                *(uint32_t*)(Ch + row * DIN + col) =
                    (uint32_t)h0u | ((uint32_t)h1u << 16);
                *(uint32_t*)(Cl + row * DIN + col) =
                    packbf(v0 - __bfloat162float(h0), v1 - __bfloat162float(h1));
            }
        }
    }
}

// Output projection: fp32 result to d_out.
__global__ __launch_bounds__(256, 2) void gemm_out(
    const __nv_bfloat16* __restrict__ Ah, const __nv_bfloat16* __restrict__ Al,
    const __nv_bfloat16* __restrict__ Bh, const __nv_bfloat16* __restrict__ Bl,
    const float* __restrict__ bias, float* __restrict__ C)
{
    extern __shared__ __nv_bfloat16 smem[];
    const uint32_t sb = smem_u32(smem);
    const int t = threadIdx.x, wid = t >> 5, lane = t & 31;
    const int m0 = blockIdx.y * 128, n0 = blockIdx.x * 128;

    const __nv_bfloat16* srcs[4] = {
        Ah + (long)m0 * DIN, Al + (long)m0 * DIN,
        Bh + (long)n0 * DIN, Bl + (long)n0 * DIN };

    float acc[4][4][4];
#pragma unroll
    for (int i = 0; i < 4; i++)
#pragma unroll
        for (int j = 0; j < 4; j++)
#pragma unroll
            for (int e = 0; e < 4; e++) acc[i][j][e] = 0.f;

    gemm_core(sb, srcs, acc, t, wid, lane);

    const int wm = (wid >> 2) * 64;
    const int wn = (wid & 3) * 32;
    const int em = lane >> 2;
    const int en = (lane & 3) * 2;
#pragma unroll
    for (int mf = 0; mf < 4; mf++) {
#pragma unroll
        for (int half = 0; half < 2; half++) {
            long row = m0 + wm + mf * 16 + em + half * 8;
#pragma unroll
            for (int nf = 0; nf < 4; nf++) {
                int col = n0 + wn + nf * 8 + en;
                float2 v;
                v.x = acc[mf][nf][half * 2 + 0] + bias[col + 0];
                v.y = acc[mf][nf][half * 2 + 1] + bias[col + 1];
                *(float2*)(C + row * DIN + col) = v;
            }
        }
    }
}

// ============ flash attention (mma.sync, cp.async double-buffered KV) ========
// Scores arrive pre-scaled by 0.125*log2e; softmax uses exp2f.
#define AST 72
#define FA_Q_UNITS (128 * AST)             // 9216
#define FA_KV_TILE (64 * AST)              // 4608
#define FA_STAGE_UNITS (4 * FA_KV_TILE)    // 18432
#define SMEM_FA ((2 * FA_Q_UNITS + 2 * FA_STAGE_UNITS) * 2)   // 110592 bytes

__device__ __forceinline__ void issue_kv(uint32_t dbase,
                                         const __nv_bfloat16* const* gkv,
                                         long off, int t) {
#pragma unroll
    for (int i = 0; i < 8; i++) {
        int u = t + 256 * i;            // 0..2047
        int w = u >> 9;
        int rem = u & 511;
        int r = rem >> 3;               // 0..63
        int c = rem & 7;                // 0..7 (8 x 16B = full 128B row)
        uint32_t dst = dbase + (uint32_t)(w * FA_KV_TILE + r * AST + c * 8) * 2;
        cp16(dst, gkv[w] + off + (long)r * DIN + c * 8);
    }
}

__global__ __launch_bounds__(256, 2) void flash_mma_kernel() {
    extern __shared__ __nv_bfloat16 sm[];
    const uint32_t sb = smem_u32(sm);
    const int t = threadIdx.x, warp = t >> 5, lane = t & 31;
    const int b = blockIdx.z, h = blockIdx.y;
    const int q0 = blockIdx.x * 128;

    __nv_bfloat16* sQh = sm;
    __nv_bfloat16* sQl = sm + FA_Q_UNITS;
    const uint32_t bQh = sb;
    const uint32_t bQl = sb + FA_Q_UNITS * 2;
    const uint32_t bKV = sb + 2 * FA_Q_UNITS * 2;   // stage0 base (bytes)

    const int a_r  = (lane & 7) + ((lane >> 3) & 1) * 8;
    const int a_kk = (lane >> 4) * 8;
    const int b_n  = (lane & 7) + (lane >> 4) * 8;
    const int b_kk = ((lane >> 3) & 1) * 8;
    const int v_kv = (lane & 7) + ((lane >> 3) & 1) * 8;
    const int v_d  = (lane >> 4) * 8;

    const long kvbase0 = (long)(b * SS) * DIN + h * DH;
    const __nv_bfloat16* gkv[4];
    gkv[0] = g_Kh + kvbase0; gkv[1] = g_Kl + kvbase0;
    gkv[2] = g_Vh + kvbase0; gkv[3] = g_Vl + kvbase0;

    issue_kv(bKV, gkv, 0, t);
    CP_COMMIT();

    {
        long base = (long)(b * SS + q0) * DIN + h * DH;
#pragma unroll
        for (int i = 0; i < 4; i++) {
            int u = t + 256 * i;
            int r = u >> 3, c = u & 7;
            *(uint4*)(sQh + r * AST + c * 8) = *(const uint4*)(g_Qh + base + (long)r * DIN + c * 8);
            *(uint4*)(sQl + r * AST + c * 8) = *(const uint4*)(g_Ql + base + (long)r * DIN + c * 8);
        }
    }

    float oacc[8][4];
#pragma unroll
    for (int i = 0; i < 8; i++)
#pragma unroll
        for (int j = 0; j < 4; j++) oacc[i][j] = 0.f;
    float m0 = -1e30f, m1 = -1e30f, sl0 = 0.f, sl1 = 0.f;

    const int NKB = SS / 64;
    for (int kb = 0; kb < NKB; kb++) {
        const int cur = kb & 1;
        CP_WAIT0();
        __syncthreads();
        if (kb + 1 < NKB) {
            issue_kv(bKV + (uint32_t)((1 - cur) * FA_STAGE_UNITS) * 2,
                     gkv, (long)(kb + 1) * 64 * DIN, t);
            CP_COMMIT();
        }

        const uint32_t bKh = bKV + (uint32_t)(cur * FA_STAGE_UNITS) * 2;
        const uint32_t bKl = bKh + FA_KV_TILE * 2;
        const uint32_t bVh = bKl + FA_KV_TILE * 2;
        const uint32_t bVl = bVh + FA_KV_TILE * 2;

        // ---- QK^T (split); scores already in log2 domain
        float sacc[8][4];
#pragma unroll
        for (int i = 0; i < 8; i++)
#pragma unroll
            for (int j = 0; j < 4; j++) sacc[i][j] = 0.f;

#pragma unroll
        for (int ks = 0; ks < 4; ks++) {
            uint32_t ah[4], al[4];
            uint32_t qoff = (uint32_t)((warp * 16 + a_r) * AST + ks * 16 + a_kk) * 2;
            ldsm4(ah, bQh + qoff);
            ldsm4(al, bQl + qoff);
#pragma unroll
            for (int g = 0; g < 4; g++) {
                uint32_t kh4[4], kl4[4];
                uint32_t koff = (uint32_t)((g * 16 + b_n) * AST + ks * 16 + b_kk) * 2;
                ldsm4(kh4, bKh + koff);
                ldsm4(kl4, bKl + koff);
                mma16816(sacc[g * 2],     ah, kh4);
                mma16816(sacc[g * 2],     ah, kl4);
                mma16816(sacc[g * 2],     al, kh4);
                mma16816(sacc[g * 2 + 1], ah, kh4 + 2);
                mma16816(sacc[g * 2 + 1], ah, kl4 + 2);
                mma16816(sacc[g * 2 + 1], al, kh4 + 2);
            }
        }

        // ---- online softmax in exp2 domain
        float mx0 = -1e30f, mx1 = -1e30f;
#pragma unroll
        for (int nf = 0; nf < 8; nf++) {
            mx0 = fmaxf(mx0, fmaxf(sacc[nf][0], sacc[nf][1]));
            mx1 = fmaxf(mx1, fmaxf(sacc[nf][2], sacc[nf][3]));
        }
        mx0 = fmaxf(mx0, __shfl_xor_sync(0xffffffffu, mx0, 1));
        mx0 = fmaxf(mx0, __shfl_xor_sync(0xffffffffu, mx0, 2));
        mx1 = fmaxf(mx1, __shfl_xor_sync(0xffffffffu, mx1, 1));
        mx1 = fmaxf(mx1, __shfl_xor_sync(0xffffffffu, mx1, 2));

        float nm0 = fmaxf(m0, mx0), nm1 = fmaxf(m1, mx1);
        float al0 = exp2f(m0 - nm0), al1 = exp2f(m1 - nm1);
        float rs0 = 0.f, rs1 = 0.f;
#pragma unroll
        for (int nf = 0; nf < 8; nf++) {
            sacc[nf][0] = exp2f(sacc[nf][0] - nm0);
            sacc[nf][1] = exp2f(sacc[nf][1] - nm0);
            sacc[nf][2] = exp2f(sacc[nf][2] - nm1);
            sacc[nf][3] = exp2f(sacc[nf][3] - nm1);
            rs0 += sacc[nf][0] + sacc[nf][1];
            rs1 += sacc[nf][2] + sacc[nf][3];
        }
        rs0 += __shfl_xor_sync(0xffffffffu, rs0, 1);
        rs0 += __shfl_xor_sync(0xffffffffu, rs0, 2);
        rs1 += __shfl_xor_sync(0xffffffffu, rs1, 1);
        rs1 += __shfl_xor_sync(0xffffffffu, rs1, 2);
        sl0 = sl0 * al0 + rs0;  m0 = nm0;
        sl1 = sl1 * al1 + rs1;  m1 = nm1;
#pragma unroll
        for (int gd = 0; gd < 8; gd++) {
            oacc[gd][0] *= al0;  oacc[gd][1] *= al0;
            oacc[gd][2] *= al1;  oacc[gd][3] *= al1;
        }

        // ---- P -> bf16 A-fragments (hi + residual lo)
        uint32_t ph[4][4], pl[4][4];
#pragma unroll
        for (int ks = 0; ks < 4; ks++) {
#pragma unroll
            for (int q = 0; q < 2; q++) {
                int nf = 2 * ks + q;
#pragma unroll
                for (int hf = 0; hf < 2; hf++) {
                    float p0 = sacc[nf][hf * 2 + 0];
                    float p1 = sacc[nf][hf * 2 + 1];
                    __nv_bfloat16 b0 = __float2bfloat16(p0);
                    __nv_bfloat16 b1 = __float2bfloat16(p1);
                    uint16_t b0u = *(uint16_t*)&b0, b1u = *(uint16_t*)&b1;
                    ph[ks][q * 2 + hf] = (uint32_t)b0u | ((uint32_t)b1u << 16);
                    pl[ks][q * 2 + hf] = packbf(p0 - __bfloat162float(b0),
                                                p1 - __bfloat162float(b1));
                }
            }
        }

        // ---- PV (split)
#pragma unroll
        for (int ks = 0; ks < 4; ks++) {
#pragma unroll
            for (int g = 0; g < 4; g++) {
                uint32_t vh4[4], vl4[4];
                uint32_t voff = (uint32_t)((ks * 16 + v_kv) * AST + g * 16 + v_d) * 2;
                ldsm4t(vh4, bVh + voff);
                ldsm4t(vl4, bVl + voff);
                mma16816(oacc[g * 2],     ph[ks], vh4);
                mma16816(oacc[g * 2],     ph[ks], vl4);
                mma16816(oacc[g * 2],     pl[ks], vh4);
                mma16816(oacc[g * 2 + 1], ph[ks], vh4 + 2);
                mma16816(oacc[g * 2 + 1], ph[ks], vl4 + 2);
                mma16816(oacc[g * 2 + 1], pl[ks], vh4 + 2);
            }
        }
    }

    // ---- epilogue: normalize, split, write [row][h*64+d]
    float inv0 = 1.f / sl0, inv1 = 1.f / sl1;
    long row0 = (long)(b * SS + q0 + warp * 16 + (lane >> 2));
    int colb = h * DH + (lane & 3) * 2;
#pragma unroll
    for (int gd = 0; gd < 8; gd++) {
        int col = colb + gd * 8;
        {
            float v0 = oacc[gd][0] * inv0, v1 = oacc[gd][1] * inv0;
            __nv_bfloat16 h0 = __float2bfloat16(v0), h1 = __float2bfloat16(v1);
            uint16_t h0u = *(uint16_t*)&h0, h1u = *(uint16_t*)&h1;
            *(uint32_t*)(g_Oh + row0 * DIN + col) = (uint32_t)h0u | ((uint32_t)h1u << 16);
            *(uint32_t*)(g_Ol + row0 * DIN + col) =
                packbf(v0 - __bfloat162float(h0), v1 - __bfloat162float(h1));
        }
        {
            float v0 = oacc[gd][2] * inv1, v1 = oacc[gd][3] * inv1;
            __nv_bfloat16 h0 = __float2bfloat16(v0), h1 = __float2bfloat16(v1);
            uint16_t h0u = *(uint16_t*)&h0, h1u = *(uint16_t*)&h1;
            *(uint32_t*)(g_Oh + (row0 + 8) * DIN + col) = (uint32_t)h0u | ((uint32_t)h1u << 16);
            *(uint32_t*)(g_Ol + (row0 + 8) * DIN + col) =
                packbf(v0 - __bfloat162float(h0), v1 - __bfloat162float(h1));
        }
    }
}

// ---------------- launcher ---------------------------------------------------
extern "C" void kernel_launch(void* const* d_in, const int* in_sizes, int n_in,
                              void* d_out, int out_size) {
    const float* query = (const float*)d_in[0];
    const float* key_  = (const float*)d_in[1];
    const float* value = (const float*)d_in[2];
    const float* Wq = (const float*)d_in[3];
    const float* bq = (const float*)d_in[4];
    const float* Wk = (const float*)d_in[5];
    const float* bk = (const float*)d_in[6];
    const float* Wv = (const float*)d_in[7];
    const float* bv = (const float*)d_in[8];
    const float* Wo = (const float*)d_in[9];
    const float* bo = (const float*)d_in[10];
    float* out = (float*)d_out;

    __nv_bfloat16 *pWh, *pWl, *pOh, *pOl;
    cudaGetSymbolAddress((void**)&pWh, g_Wh);
    cudaGetSymbolAddress((void**)&pWl, g_Wl);
    cudaGetSymbolAddress((void**)&pOh, g_Oh);
    cudaGetSymbolAddress((void**)&pOl, g_Ol);

    cudaFuncSetAttribute(gemm_qkv,
                         cudaFuncAttributeMaxDynamicSharedMemorySize, SMEM_GEMM);
    cudaFuncSetAttribute(gemm_out,
                         cudaFuncAttributeMaxDynamicSharedMemorySize, SMEM_GEMM);
    cudaFuncSetAttribute(flash_mma_kernel,
                         cudaFuncAttributeMaxDynamicSharedMemorySize, SMEM_FA);

    wsplit_kernel<<<dim3(DIN * DIN / 256, 4), 256>>>(Wq, Wk, Wv, Wo);

    const int splitBlocks = XSZ / 4 / 256;
    split3_kernel<<<dim3(splitBlocks, 3), 256>>>(
        (const float4*)query, (const float4*)key_, (const float4*)value);

    gemm_qkv<<<dim3(DIN / 128, MROWS / 128, 3), 256, SMEM_GEMM>>>(bq, bk, bv);

    flash_mma_kernel<<<dim3(SS / 128, HH, BB), 256, SMEM_FA>>>();

    gemm_out<<<dim3(DIN / 128, MROWS / 128), 256, SMEM_GEMM>>>(
        pOh, pOl, pWh + 3 * DIN * DIN, pWl + 3 * DIN * DIN, bo, out);
}